// round 6
// baseline (speedup 1.0000x reference)
#include <cuda_runtime.h>
#include <cstdint>
#include <math.h>

#define D_DIM 1024
#define H_DIM 512
#define E_NUM 16
#define NTOK  4096
#define KSEL  8
#define NK    (NTOK * KSEL)

// ---------------------------------------------------------------------------
// Device scratch
// ---------------------------------------------------------------------------
__device__ float g_gwn[E_NUM * D_DIM];
__device__ int   g_idx[NK];
__device__ float g_w[NK];
__device__ int   g_cnt[E_NUM];
__device__ int   g_pos[E_NUM];
__device__ int   g_tok[NK + 128];
__device__ float g_tw[NK + 128];
__device__ int   g_pmap[NK];

__device__ float g_xt[(size_t)NTOK * D_DIM];                // tf32-rounded x
__device__ float g_wguT[(size_t)E_NUM * 2 * H_DIM * D_DIM]; // [E][2H][D] interleaved gate/up
__device__ float g_wdT [(size_t)E_NUM * D_DIM * H_DIM];     // [E][D][H]
__device__ float g_swguT[(size_t)2 * H_DIM * D_DIM];
__device__ float g_swdT [(size_t)D_DIM * H_DIM];

__device__ float g_h [((size_t)NK + 128) * H_DIM];          // routed hidden (weighted, rounded)
__device__ float g_hs[(size_t)NTOK * H_DIM];                // shared hidden
__device__ float g_y [(size_t)NK * D_DIM];                  // routed down output

// ---------------------------------------------------------------------------
// Helpers (sm_80-compatible PTX only — harness compiles for plain sm_100)
// ---------------------------------------------------------------------------
__device__ __forceinline__ uint32_t smem_u32(const void* p) {
    uint32_t a;
    asm("{ .reg .u64 t; cvta.to.shared.u64 t, %1; cvt.u32.u64 %0, t; }" : "=r"(a) : "l"(p));
    return a;
}
__device__ __forceinline__ void cp16(uint32_t dst, const void* src) {
    asm volatile("cp.async.cg.shared.global [%0], [%1], 16;" :: "r"(dst), "l"(src));
}
#define CP_COMMIT() asm volatile("cp.async.commit_group;" ::: "memory")
#define CP_WAIT1()  asm volatile("cp.async.wait_group 1;" ::: "memory")

__device__ __forceinline__ float tf32r(float f) {
    uint32_t o;
    asm("cvt.rna.tf32.f32 %0, %1;" : "=r"(o) : "f"(f));
    return __uint_as_float(o);
}
__device__ __forceinline__ void ldm4(uint32_t& r0, uint32_t& r1, uint32_t& r2, uint32_t& r3,
                                     uint32_t a) {
    asm volatile("ldmatrix.sync.aligned.m8n8.x4.shared.b16 {%0,%1,%2,%3}, [%4];"
                 : "=r"(r0), "=r"(r1), "=r"(r2), "=r"(r3) : "r"(a));
}
__device__ __forceinline__ void mma8(float* c, const uint32_t* a, uint32_t b0, uint32_t b1) {
    asm volatile("mma.sync.aligned.m16n8k8.row.col.f32.tf32.tf32.f32 "
                 "{%0,%1,%2,%3}, {%4,%5,%6,%7}, {%8,%9}, {%0,%1,%2,%3};"
                 : "+f"(c[0]), "+f"(c[1]), "+f"(c[2]), "+f"(c[3])
                 : "r"(a[0]), "r"(a[1]), "r"(a[2]), "r"(a[3]), "r"(b0), "r"(b1));
}

// ---------------------------------------------------------------------------
// Gating path (exact fp32 — must match reference routing)
// ---------------------------------------------------------------------------
__global__ void gwnorm_kernel(const float* __restrict__ gw) {
    int e = blockIdx.x, t = threadIdx.x;
    if (e == 0 && t < E_NUM) { g_cnt[t] = 0; g_pos[t] = 0; }
    __shared__ float red[8];
    float ss = 0.f;
    for (int i = t; i < D_DIM; i += 256) { float v = gw[e * D_DIM + i]; ss += v * v; }
    for (int o = 16; o; o >>= 1) ss += __shfl_down_sync(0xFFFFFFFFu, ss, o);
    if ((t & 31) == 0) red[t >> 5] = ss;
    __syncthreads();
    __shared__ float s_inv;
    if (t == 0) {
        float tot = 0.f;
        for (int i = 0; i < 8; i++) tot += red[i];
        s_inv = 1.0f / fmaxf(sqrtf(tot), 1e-12f);
    }
    __syncthreads();
    float inv = s_inv;
    for (int i = t; i < D_DIM; i += 256) g_gwn[e * D_DIM + i] = gw[e * D_DIM + i] * inv;
}

// Also emits the tf32-rounded copy of x (g_xt).
__global__ void gating_kernel(const float* __restrict__ x) {
    int n = blockIdx.x, t = threadIdx.x;
    int warp = t >> 5, lane = t & 31;
    __shared__ float sx[D_DIM];
    __shared__ float red[8];
    __shared__ float slog[E_NUM];
    const float* xr = x + (size_t)n * D_DIM;
    float ss = 0.f;
    for (int i = t; i < D_DIM; i += 256) { float v = xr[i]; sx[i] = v; ss += v * v; }
    for (int o = 16; o; o >>= 1) ss += __shfl_down_sync(0xFFFFFFFFu, ss, o);
    if (lane == 0) red[warp] = ss;
    __syncthreads();
    for (int i = t; i < D_DIM; i += 256) g_xt[(size_t)n * D_DIM + i] = tf32r(sx[i]);
    for (int j = 0; j < 2; j++) {
        int e = warp * 2 + j;
        const float* g = g_gwn + e * D_DIM;
        float d = 0.f;
        for (int i = lane; i < D_DIM; i += 32) d += sx[i] * g[i];
        for (int o = 16; o; o >>= 1) d += __shfl_down_sync(0xFFFFFFFFu, d, o);
        if (lane == 0) slog[e] = d;
    }
    __syncthreads();
    if (t == 0) {
        float ssq = 0.f;
        for (int i = 0; i < 8; i++) ssq += red[i];
        float inv = 1.0f / fmaxf(sqrtf(ssq), 1e-12f);
        float sc[E_NUM];
        for (int e = 0; e < E_NUM; e++) sc[e] = slog[e] * inv;
        int sel[KSEL]; float sw[KSEL]; float wsum = 0.f;
        for (int k = 0; k < KSEL; k++) {
            int bi = 0; float bv = -1e30f;
            for (int e = 0; e < E_NUM; e++)
                if (sc[e] > bv) { bv = sc[e]; bi = e; }
            sel[k] = bi;
            float s = 1.0f / (1.0f + __expf(-bv));
            sw[k] = s; wsum += s; sc[bi] = -1e30f;
        }
        float invw = 1.0f / wsum;
        for (int k = 0; k < KSEL; k++) {
            g_idx[n * KSEL + k] = sel[k];
            g_w[n * KSEL + k]   = sw[k] * invw;
            atomicAdd(&g_cnt[sel[k]], 1);
        }
    }
}

// scatter with in-block prefix over g_cnt (scan kernel folded in)
__global__ void scatter_kernel() {
    __shared__ int soff[E_NUM];
    int t = threadIdx.x;
    if (t == 0) {
        int a = 0;
        for (int e = 0; e < E_NUM; e++) { soff[e] = a; a += g_cnt[e]; }
    }
    __syncthreads();
    int id = blockIdx.x * 256 + t;
    if (id < NK) {
        int e = g_idx[id];
        int p = soff[e] + atomicAdd(&g_pos[e], 1);
        g_tok[p] = id / KSEL;
        g_tw[p]  = g_w[id];
        g_pmap[id] = p;
    }
}

// ---------------------------------------------------------------------------
// Fused weight prep: all 6 transposes (+tf32 round, +gate/up interleave) in
// one launch. grid = (32, 32, 51); blocks outside a job's extent exit early.
// ---------------------------------------------------------------------------
__global__ void prep_kernel(const float* __restrict__ wg, const float* __restrict__ wu,
                            const float* __restrict__ wd, const float* __restrict__ swg,
                            const float* __restrict__ swu, const float* __restrict__ swd,
                            float* __restrict__ wguT, float* __restrict__ wdT,
                            float* __restrict__ swguT, float* __restrict__ swdT) {
    int z = blockIdx.z;
    const float* src; float* dst;
    int R, C, mul, add;
    size_t bi, bo;
    if (z < 16)       { int e = z;      src = wg;  dst = wguT;  R = D_DIM; C = H_DIM; mul = 2; add = 0; bi = (size_t)e * R * C; bo = bi * 2; }
    else if (z < 32)  { int e = z - 16; src = wu;  dst = wguT;  R = D_DIM; C = H_DIM; mul = 2; add = 1; bi = (size_t)e * R * C; bo = bi * 2; }
    else if (z < 48)  { int e = z - 32; src = wd;  dst = wdT;   R = H_DIM; C = D_DIM; mul = 1; add = 0; bi = (size_t)e * R * C; bo = bi; }
    else if (z == 48) { src = swg; dst = swguT; R = D_DIM; C = H_DIM; mul = 2; add = 0; bi = 0; bo = 0; }
    else if (z == 49) { src = swu; dst = swguT; R = D_DIM; C = H_DIM; mul = 2; add = 1; bi = 0; bo = 0; }
    else              { src = swd; dst = swdT;  R = H_DIM; C = D_DIM; mul = 1; add = 0; bi = 0; bo = 0; }

    int c0 = blockIdx.x * 32, r0 = blockIdx.y * 32;
    if (c0 >= C || r0 >= R) return;

    __shared__ float tile[32][33];
    int tx = threadIdx.x, ty = threadIdx.y;
#pragma unroll
    for (int j = 0; j < 32; j += 8)
        tile[ty + j][tx] = src[bi + (size_t)(r0 + ty + j) * C + c0 + tx];
    __syncthreads();
#pragma unroll
    for (int j = 0; j < 32; j += 8)
        dst[bo + (size_t)((c0 + ty + j) * mul + add) * R + r0 + tx] = tf32r(tile[tx][ty + j]);
}

// ---------------------------------------------------------------------------
// tf32 mma.sync GEMM. Block 128x128, BK=32, 256 threads, warp grid 2(m)x4(n).
// 3-stage cp.async pipeline, ONE __syncthreads per K-chunk. 2 CTAs/SM.
// ---------------------------------------------------------------------------
#define TSTRIDE 36
#define TILE_F  (128 * TSTRIDE)
#define TILE_B  (TILE_F * 4)
#define NSTG    3
#define SMEM_BYTES (2 * NSTG * TILE_B + 128 * 8)

template <bool GATHER, bool GU>
__global__ void __launch_bounds__(256, 2)
mma_gemm(const float* __restrict__ A, const float* __restrict__ B, float* __restrict__ out) {
    constexpr int KD = GU ? D_DIM : H_DIM;
    const int e   = blockIdx.z;
    const int cnt = GATHER ? g_cnt[e] : NTOK;
    const int m0  = blockIdx.x * 128;
    if (m0 >= cnt) return;
    int offr = 0;
    if (GATHER) {
        for (int q = 0; q < E_NUM; q++) offr += (q < e) ? g_cnt[q] : 0;
    }
    const int n0 = blockIdx.y * 128;

    extern __shared__ float smf[];
    float* As = smf;                              // NSTG stages
    float* Bs = smf + NSTG * TILE_F;
    int*   rtok = (int*)(smf + 2 * NSTG * TILE_F);
    float* twsh = smf + 2 * NSTG * TILE_F + 128;

    const int t = threadIdx.x;
    const int warp = t >> 5, lane = t & 31;
    const int wm = warp >> 2, wn = warp & 3;

    if (t < 128) {
        int gm = m0 + t;
        int cg = (gm < cnt) ? gm : 0;
        int src;
        if (GU) src = GATHER ? g_tok[offr + cg] : gm;
        else    src = offr + gm;
        rtok[t] = src;
        twsh[t] = (GU && GATHER) ? g_tw[offr + cg] : 1.0f;
    }
    __syncthreads();

    const uint32_t uA = smem_u32(As);
    const uint32_t uB = smem_u32(Bs);

    const size_t eoff = GATHER ? (size_t)e * 1024 * KD : 0;
    const float* aP[4];
    const float* bP[4];
    uint32_t sOff[4];
#pragma unroll
    for (int j = 0; j < 4; j++) {
        int cidx = t + j * 256;
        int row = cidx >> 3, kc = cidx & 7;
        aP[j] = A + (size_t)rtok[row] * KD + kc * 4;
        bP[j] = B + eoff + (size_t)(n0 + row) * KD + kc * 4;
        sOff[j] = (uint32_t)(row * (TSTRIDE * 4) + kc * 16);
    }

#define LOADSTAGE(s, k0) do {                                       \
        _Pragma("unroll")                                           \
        for (int j = 0; j < 4; j++) {                               \
            cp16(uA + (s) * TILE_B + sOff[j], aP[j] + (k0));        \
            cp16(uB + (s) * TILE_B + sOff[j], bP[j] + (k0));        \
        }                                                           \
    } while (0)

    float c[4][4][4] = {};

    const int NIT = KD / 32;
    LOADSTAGE(0, 0);  CP_COMMIT();
    LOADSTAGE(1, 32); CP_COMMIT();

    for (int i = 0; i < NIT; i++) {
        CP_WAIT1();                 // stage i landed (stage i+1 may pend)
        __syncthreads();            // data visible + WAR-safe for stage (i-1)%3
        const int ld = i + 2;
        if (ld < NIT) LOADSTAGE(ld % NSTG, ld * 32);
        CP_COMMIT();                // empty group at tail keeps accounting simple

        const int s = i % NSTG;
        const uint32_t uAs = uA + s * TILE_B;
        const uint32_t uBs = uB + s * TILE_B;
#pragma unroll
        for (int ks = 0; ks < 4; ks++) {
            uint32_t a[4][4], b[2][4];
#pragma unroll
            for (int mt = 0; mt < 4; mt++) {
                uint32_t row = wm * 64 + mt * 16 + (lane & 7) + ((lane >> 3) & 1) * 8;
                uint32_t ad = uAs + row * (TSTRIDE * 4) + ks * 32 + (lane >> 4) * 16;
                ldm4(a[mt][0], a[mt][1], a[mt][2], a[mt][3], ad);
            }
#pragma unroll
            for (int p = 0; p < 2; p++) {
                uint32_t row = wn * 32 + p * 16 + ((lane >> 4) & 1) * 8 + (lane & 7);
                uint32_t ad = uBs + row * (TSTRIDE * 4) + ks * 32 + ((lane >> 3) & 1) * 16;
                ldm4(b[p][0], b[p][1], b[p][2], b[p][3], ad);
            }
#pragma unroll
            for (int mt = 0; mt < 4; mt++) {
#pragma unroll
                for (int nt = 0; nt < 4; nt++)
                    mma8(c[mt][nt], a[mt], b[nt >> 1][2 * (nt & 1)], b[nt >> 1][2 * (nt & 1) + 1]);
            }
        }
    }
#undef LOADSTAGE

    const int obase_row = GATHER ? offr : 0;
#pragma unroll
    for (int mt = 0; mt < 4; mt++) {
        int r0 = wm * 64 + mt * 16 + (lane >> 2);
#pragma unroll
        for (int pass = 0; pass < 2; pass++) {
            int r = r0 + pass * 8;
            int gm = m0 + r;
            if (gm < cnt) {
                if (GU) {
                    float tw = twsh[r];
                    float* orow = out + (size_t)(obase_row + gm) * H_DIM;
#pragma unroll
                    for (int nt = 0; nt < 4; nt++) {
                        float g = c[mt][nt][pass * 2];
                        float u = c[mt][nt][pass * 2 + 1];
                        int h = (n0 + wn * 32 + nt * 8) / 2 + (lane & 3);
                        orow[h] = tf32r(tw * u * g / (1.0f + __expf(-g)));
                    }
                } else {
                    float* orow = out + (size_t)(obase_row + gm) * D_DIM;
#pragma unroll
                    for (int nt = 0; nt < 4; nt++) {
                        int n = n0 + wn * 32 + nt * 8 + 2 * (lane & 3);
                        float2 v = make_float2(c[mt][nt][pass * 2], c[mt][nt][pass * 2 + 1]);
                        *(float2*)(orow + n) = v;
                    }
                }
            }
        }
    }
}

// ---------------------------------------------------------------------------
// combine: out[n] += sum_k g_y[pmap[n,k]]
// ---------------------------------------------------------------------------
__global__ void combine_kernel(float* __restrict__ out) {
    const int n = blockIdx.x, t = threadIdx.x;
    __shared__ int pm[KSEL];
    if (t < KSEL) pm[t] = g_pmap[n * KSEL + t];
    __syncthreads();
    float4 acc = *(const float4*)(out + (size_t)n * D_DIM + t * 4);
#pragma unroll
    for (int k = 0; k < KSEL; k++) {
        float4 v = *(const float4*)(g_y + (size_t)pm[k] * D_DIM + t * 4);
        acc.x += v.x; acc.y += v.y; acc.z += v.z; acc.w += v.w;
    }
    *(float4*)(out + (size_t)n * D_DIM + t * 4) = acc;
}

// ---------------------------------------------------------------------------
// Launch
// ---------------------------------------------------------------------------
extern "C" void kernel_launch(void* const* d_in, const int* in_sizes, int n_in,
                              void* d_out, int out_size) {
    (void)in_sizes; (void)n_in; (void)out_size;
    const float* x       = (const float*)d_in[0];
    const float* gate_w  = (const float*)d_in[1];
    const float* w_gate  = (const float*)d_in[2];
    const float* w_up    = (const float*)d_in[3];
    const float* w_down  = (const float*)d_in[4];
    const float* sw_gate = (const float*)d_in[5];
    const float* sw_up   = (const float*)d_in[6];
    const float* sw_down = (const float*)d_in[7];
    float* out = (float*)d_out;

    cudaFuncSetAttribute(mma_gemm<true, true>,   cudaFuncAttributeMaxDynamicSharedMemorySize, SMEM_BYTES);
    cudaFuncSetAttribute(mma_gemm<true, false>,  cudaFuncAttributeMaxDynamicSharedMemorySize, SMEM_BYTES);
    cudaFuncSetAttribute(mma_gemm<false, true>,  cudaFuncAttributeMaxDynamicSharedMemorySize, SMEM_BYTES);
    cudaFuncSetAttribute(mma_gemm<false, false>, cudaFuncAttributeMaxDynamicSharedMemorySize, SMEM_BYTES);

    float* xt; float* wguT; float* wdT; float* swguT; float* swdT;
    float* hbuf; float* hsbuf; float* ybuf;
    cudaGetSymbolAddress((void**)&xt,    g_xt);
    cudaGetSymbolAddress((void**)&wguT,  g_wguT);
    cudaGetSymbolAddress((void**)&wdT,   g_wdT);
    cudaGetSymbolAddress((void**)&swguT, g_swguT);
    cudaGetSymbolAddress((void**)&swdT,  g_swdT);
    cudaGetSymbolAddress((void**)&hbuf,  g_h);
    cudaGetSymbolAddress((void**)&hsbuf, g_hs);
    cudaGetSymbolAddress((void**)&ybuf,  g_y);

    gwnorm_kernel<<<E_NUM, 256>>>(gate_w);
    gating_kernel<<<NTOK, 256>>>(x);
    scatter_kernel<<<(NK + 255) / 256, 256>>>();

    // all weight prep in one launch
    prep_kernel<<<dim3(32, 32, 51), dim3(32, 8)>>>(
        w_gate, w_up, w_down, sw_gate, sw_up, sw_down, wguT, wdT, swguT, swdT);

    // shared expert (initializes out)
    mma_gemm<false, true><<<dim3(NTOK / 128, 8, 1), 256, SMEM_BYTES>>>(xt, swguT, hsbuf);
    mma_gemm<false, false><<<dim3(NTOK / 128, 8, 1), 256, SMEM_BYTES>>>(hsbuf, swdT, out);

    // routed experts
    mma_gemm<true, true><<<dim3(NTOK / 128, 8, E_NUM), 256, SMEM_BYTES>>>(xt, wguT, hbuf);
    mma_gemm<true, false><<<dim3(NTOK / 128, 8, E_NUM), 256, SMEM_BYTES>>>(hbuf, wdT, ybuf);

    combine_kernel<<<NTOK, 256>>>(out);
}

// round 7
// speedup vs baseline: 1.6209x; 1.6209x over previous
#include <cuda_runtime.h>
#include <cuda_fp16.h>
#include <cstdint>
#include <math.h>

#define D_DIM 1024
#define H_DIM 512
#define E_NUM 16
#define NTOK  4096
#define KSEL  8
#define NK    (NTOK * KSEL)

// ---------------------------------------------------------------------------
// Device scratch
// ---------------------------------------------------------------------------
__device__ float g_gwn[E_NUM * D_DIM];
__device__ int   g_idx[NK];
__device__ float g_w[NK];
__device__ int   g_cnt[E_NUM];
__device__ int   g_pos[E_NUM];
__device__ int   g_tok[NK + 128];
__device__ float g_tw[NK + 128];
__device__ int   g_pmap[NK];

__device__ __half g_xt[(size_t)NTOK * D_DIM];                // fp16 x
__device__ __half g_wguT[(size_t)E_NUM * 2 * H_DIM * D_DIM]; // [E][2H][D] interleaved gate/up
__device__ __half g_wdT [(size_t)E_NUM * D_DIM * H_DIM];     // [E][D][H]
__device__ __half g_swguT[(size_t)2 * H_DIM * D_DIM];
__device__ __half g_swdT [(size_t)D_DIM * H_DIM];

__device__ __half g_h [((size_t)NK + 128) * H_DIM];          // routed hidden (weighted)
__device__ __half g_hs[(size_t)NTOK * H_DIM];                // shared hidden
__device__ float  g_y [(size_t)NK * D_DIM];                  // routed down output (fp32)

// ---------------------------------------------------------------------------
// Helpers (sm_80-compatible PTX only — harness compiles for plain sm_100)
// ---------------------------------------------------------------------------
__device__ __forceinline__ uint32_t smem_u32(const void* p) {
    uint32_t a;
    asm("{ .reg .u64 t; cvta.to.shared.u64 t, %1; cvt.u32.u64 %0, t; }" : "=r"(a) : "l"(p));
    return a;
}
__device__ __forceinline__ void cp16(uint32_t dst, const void* src) {
    asm volatile("cp.async.cg.shared.global [%0], [%1], 16;" :: "r"(dst), "l"(src));
}
#define CP_COMMIT() asm volatile("cp.async.commit_group;" ::: "memory")
#define CP_WAIT1()  asm volatile("cp.async.wait_group 1;" ::: "memory")

__device__ __forceinline__ void ldm4(uint32_t& r0, uint32_t& r1, uint32_t& r2, uint32_t& r3,
                                     uint32_t a) {
    asm volatile("ldmatrix.sync.aligned.m8n8.x4.shared.b16 {%0,%1,%2,%3}, [%4];"
                 : "=r"(r0), "=r"(r1), "=r"(r2), "=r"(r3) : "r"(a));
}
__device__ __forceinline__ void mma16(float* c, const uint32_t* a, uint32_t b0, uint32_t b1) {
    asm volatile("mma.sync.aligned.m16n8k16.row.col.f32.f16.f16.f32 "
                 "{%0,%1,%2,%3}, {%4,%5,%6,%7}, {%8,%9}, {%0,%1,%2,%3};"
                 : "+f"(c[0]), "+f"(c[1]), "+f"(c[2]), "+f"(c[3])
                 : "r"(a[0]), "r"(a[1]), "r"(a[2]), "r"(a[3]), "r"(b0), "r"(b1));
}

// ---------------------------------------------------------------------------
// Gating path (exact fp32 — must match reference routing)
// ---------------------------------------------------------------------------
__global__ void gwnorm_kernel(const float* __restrict__ gw) {
    int e = blockIdx.x, t = threadIdx.x;
    if (e == 0 && t < E_NUM) { g_cnt[t] = 0; g_pos[t] = 0; }
    __shared__ float red[8];
    float ss = 0.f;
    for (int i = t; i < D_DIM; i += 256) { float v = gw[e * D_DIM + i]; ss += v * v; }
    for (int o = 16; o; o >>= 1) ss += __shfl_down_sync(0xFFFFFFFFu, ss, o);
    if ((t & 31) == 0) red[t >> 5] = ss;
    __syncthreads();
    __shared__ float s_inv;
    if (t == 0) {
        float tot = 0.f;
        for (int i = 0; i < 8; i++) tot += red[i];
        s_inv = 1.0f / fmaxf(sqrtf(tot), 1e-12f);
    }
    __syncthreads();
    float inv = s_inv;
    for (int i = t; i < D_DIM; i += 256) g_gwn[e * D_DIM + i] = gw[e * D_DIM + i] * inv;
}

// Also emits the fp16 copy of x (g_xt).
__global__ void gating_kernel(const float* __restrict__ x) {
    int n = blockIdx.x, t = threadIdx.x;
    int warp = t >> 5, lane = t & 31;
    __shared__ float sx[D_DIM];
    __shared__ float red[8];
    __shared__ float slog[E_NUM];
    const float* xr = x + (size_t)n * D_DIM;
    float ss = 0.f;
    for (int i = t; i < D_DIM; i += 256) { float v = xr[i]; sx[i] = v; ss += v * v; }
    for (int o = 16; o; o >>= 1) ss += __shfl_down_sync(0xFFFFFFFFu, ss, o);
    if (lane == 0) red[warp] = ss;
    __syncthreads();
    for (int i = t; i < D_DIM; i += 256) g_xt[(size_t)n * D_DIM + i] = __float2half_rn(sx[i]);
    for (int j = 0; j < 2; j++) {
        int e = warp * 2 + j;
        const float* g = g_gwn + e * D_DIM;
        float d = 0.f;
        for (int i = lane; i < D_DIM; i += 32) d += sx[i] * g[i];
        for (int o = 16; o; o >>= 1) d += __shfl_down_sync(0xFFFFFFFFu, d, o);
        if (lane == 0) slog[e] = d;
    }
    __syncthreads();
    if (t == 0) {
        float ssq = 0.f;
        for (int i = 0; i < 8; i++) ssq += red[i];
        float inv = 1.0f / fmaxf(sqrtf(ssq), 1e-12f);
        float sc[E_NUM];
        for (int e = 0; e < E_NUM; e++) sc[e] = slog[e] * inv;
        int sel[KSEL]; float sw[KSEL]; float wsum = 0.f;
        for (int k = 0; k < KSEL; k++) {
            int bi = 0; float bv = -1e30f;
            for (int e = 0; e < E_NUM; e++)
                if (sc[e] > bv) { bv = sc[e]; bi = e; }
            sel[k] = bi;
            float s = 1.0f / (1.0f + __expf(-bv));
            sw[k] = s; wsum += s; sc[bi] = -1e30f;
        }
        float invw = 1.0f / wsum;
        for (int k = 0; k < KSEL; k++) {
            g_idx[n * KSEL + k] = sel[k];
            g_w[n * KSEL + k]   = sw[k] * invw;
            atomicAdd(&g_cnt[sel[k]], 1);
        }
    }
}

// scatter with in-block prefix over g_cnt
__global__ void scatter_kernel() {
    __shared__ int soff[E_NUM];
    int t = threadIdx.x;
    if (t == 0) {
        int a = 0;
        for (int e = 0; e < E_NUM; e++) { soff[e] = a; a += g_cnt[e]; }
    }
    __syncthreads();
    int id = blockIdx.x * 256 + t;
    if (id < NK) {
        int e = g_idx[id];
        int p = soff[e] + atomicAdd(&g_pos[e], 1);
        g_tok[p] = id / KSEL;
        g_tw[p]  = g_w[id];
        g_pmap[id] = p;
    }
}

// ---------------------------------------------------------------------------
// Fused weight prep: all 6 transposes (+fp16 convert, +gate/up interleave).
// ---------------------------------------------------------------------------
__global__ void prep_kernel(const float* __restrict__ wg, const float* __restrict__ wu,
                            const float* __restrict__ wd, const float* __restrict__ swg,
                            const float* __restrict__ swu, const float* __restrict__ swd,
                            __half* __restrict__ wguT, __half* __restrict__ wdT,
                            __half* __restrict__ swguT, __half* __restrict__ swdT) {
    int z = blockIdx.z;
    const float* src; __half* dst;
    int R, C, mul, add;
    size_t bi, bo;
    if (z < 16)       { int e = z;      src = wg;  dst = wguT;  R = D_DIM; C = H_DIM; mul = 2; add = 0; bi = (size_t)e * R * C; bo = bi * 2; }
    else if (z < 32)  { int e = z - 16; src = wu;  dst = wguT;  R = D_DIM; C = H_DIM; mul = 2; add = 1; bi = (size_t)e * R * C; bo = bi * 2; }
    else if (z < 48)  { int e = z - 32; src = wd;  dst = wdT;   R = H_DIM; C = D_DIM; mul = 1; add = 0; bi = (size_t)e * R * C; bo = bi; }
    else if (z == 48) { src = swg; dst = swguT; R = D_DIM; C = H_DIM; mul = 2; add = 0; bi = 0; bo = 0; }
    else if (z == 49) { src = swu; dst = swguT; R = D_DIM; C = H_DIM; mul = 2; add = 1; bi = 0; bo = 0; }
    else              { src = swd; dst = swdT;  R = H_DIM; C = D_DIM; mul = 1; add = 0; bi = 0; bo = 0; }

    int c0 = blockIdx.x * 32, r0 = blockIdx.y * 32;
    if (c0 >= C || r0 >= R) return;

    __shared__ float tile[32][33];
    int tx = threadIdx.x, ty = threadIdx.y;
#pragma unroll
    for (int j = 0; j < 32; j += 8)
        tile[ty + j][tx] = src[bi + (size_t)(r0 + ty + j) * C + c0 + tx];
    __syncthreads();
#pragma unroll
    for (int j = 0; j < 32; j += 8)
        dst[bo + (size_t)((c0 + ty + j) * mul + add) * R + r0 + tx] = __float2half_rn(tile[tx][ty + j]);
}

// ---------------------------------------------------------------------------
// fp16 mma.sync GEMM. Block 128x128, BK=64 halves, 256 threads,
// warp grid 2(m)x4(n), warp tile 64x32, m16n8k16. 3-stage cp.async pipeline.
// Row stride 144B (conflict-free 16B segments mod 128B).
// ---------------------------------------------------------------------------
#define ROWB    144
#define TILE_HB (128 * ROWB)      // 18432 B per stage
#define NSTG    3
#define SMEM_BYTES (2 * NSTG * TILE_HB + 1024)

template <bool GATHER, bool GU>
__global__ void __launch_bounds__(256, 2)
mma_gemm(const __half* __restrict__ A, const __half* __restrict__ B,
         __half* __restrict__ outh, float* __restrict__ outf) {
    constexpr int KD = GU ? D_DIM : H_DIM;
    const int e   = blockIdx.z;
    const int cnt = GATHER ? g_cnt[e] : NTOK;
    const int m0  = blockIdx.x * 128;
    if (m0 >= cnt) return;
    int offr = 0;
    if (GATHER) {
        for (int q = 0; q < E_NUM; q++) offr += (q < e) ? g_cnt[q] : 0;
    }
    const int n0 = blockIdx.y * 128;

    extern __shared__ char smc[];
    const uint32_t uA = smem_u32(smc);
    const uint32_t uB = uA + NSTG * TILE_HB;
    int*   rtok = (int*)(smc + 2 * NSTG * TILE_HB);
    float* twsh = (float*)(smc + 2 * NSTG * TILE_HB + 512);

    const int t = threadIdx.x;
    const int warp = t >> 5, lane = t & 31;
    const int wm = warp >> 2, wn = warp & 3;

    if (t < 128) {
        int gm = m0 + t;
        int cg = (gm < cnt) ? gm : 0;
        int src;
        if (GU) src = GATHER ? g_tok[offr + cg] : gm;
        else    src = offr + gm;
        rtok[t] = src;
        twsh[t] = (GU && GATHER) ? g_tw[offr + cg] : 1.0f;
    }
    __syncthreads();

    // per-thread load map: 4 (row, 16B-chunk) pairs each for A and B
    const size_t eoff = GATHER ? (size_t)e * 1024 * KD : 0;
    const __half* aP[4];
    const __half* bP[4];
    uint32_t sOff[4];
#pragma unroll
    for (int j = 0; j < 4; j++) {
        int cidx = t + j * 256;
        int row = cidx >> 3, kc = cidx & 7;      // kc: which 16B (8 halves)
        aP[j] = A + (size_t)rtok[row] * KD + kc * 8;
        bP[j] = B + eoff + (size_t)(n0 + row) * KD + kc * 8;
        sOff[j] = (uint32_t)(row * ROWB + kc * 16);
    }

#define LOADSTAGE(s, k0) do {                                       \
        _Pragma("unroll")                                           \
        for (int j = 0; j < 4; j++) {                               \
            cp16(uA + (s) * TILE_HB + sOff[j], aP[j] + (k0));       \
            cp16(uB + (s) * TILE_HB + sOff[j], bP[j] + (k0));       \
        }                                                           \
    } while (0)

    float c[4][4][4] = {};

    const int NIT = KD / 64;
    LOADSTAGE(0, 0);  CP_COMMIT();
    LOADSTAGE(1, 64); CP_COMMIT();

    for (int i = 0; i < NIT; i++) {
        CP_WAIT1();
        __syncthreads();
        const int ld = i + 2;
        if (ld < NIT) LOADSTAGE(ld % NSTG, ld * 64);
        CP_COMMIT();

        const int s = i % NSTG;
        const uint32_t uAs = uA + s * TILE_HB;
        const uint32_t uBs = uB + s * TILE_HB;
#pragma unroll
        for (int ks = 0; ks < 4; ks++) {          // k16 steps within BK=64
            uint32_t a[4][4], b[2][4];
#pragma unroll
            for (int mt = 0; mt < 4; mt++) {
                uint32_t row = wm * 64 + mt * 16 + (lane & 7) + ((lane >> 3) & 1) * 8;
                uint32_t ad = uAs + row * ROWB + ks * 32 + (lane >> 4) * 16;
                ldm4(a[mt][0], a[mt][1], a[mt][2], a[mt][3], ad);
            }
#pragma unroll
            for (int p = 0; p < 2; p++) {
                uint32_t row = wn * 32 + p * 16 + ((lane >> 4) & 1) * 8 + (lane & 7);
                uint32_t ad = uBs + row * ROWB + ks * 32 + ((lane >> 3) & 1) * 16;
                ldm4(b[p][0], b[p][1], b[p][2], b[p][3], ad);
            }
#pragma unroll
            for (int mt = 0; mt < 4; mt++) {
#pragma unroll
                for (int nt = 0; nt < 4; nt++) {
                    // n-tile nt: b group p = nt>>1, n8-half = nt&1 (regs {2q,2q+1})
                    mma16(c[mt][nt], a[mt], b[nt >> 1][2 * (nt & 1)], b[nt >> 1][2 * (nt & 1) + 1]);
                }
            }
        }
    }
#undef LOADSTAGE

    const int obase_row = GATHER ? offr : 0;
#pragma unroll
    for (int mt = 0; mt < 4; mt++) {
        int r0 = wm * 64 + mt * 16 + (lane >> 2);
#pragma unroll
        for (int pass = 0; pass < 2; pass++) {
            int r = r0 + pass * 8;
            int gm = m0 + r;
            if (gm < cnt) {
                if (GU) {
                    float tw = twsh[r];
                    __half* orow = outh + (size_t)(obase_row + gm) * H_DIM;
#pragma unroll
                    for (int nt = 0; nt < 4; nt++) {
                        float g = c[mt][nt][pass * 2];
                        float u = c[mt][nt][pass * 2 + 1];
                        int h = (n0 + wn * 32 + nt * 8) / 2 + (lane & 3);
                        orow[h] = __float2half_rn(tw * u * g / (1.0f + __expf(-g)));
                    }
                } else {
                    float* orow = outf + (size_t)(obase_row + gm) * D_DIM;
#pragma unroll
                    for (int nt = 0; nt < 4; nt++) {
                        int n = n0 + wn * 32 + nt * 8 + 2 * (lane & 3);
                        float2 v = make_float2(c[mt][nt][pass * 2], c[mt][nt][pass * 2 + 1]);
                        *(float2*)(orow + n) = v;
                    }
                }
            }
        }
    }
}

// ---------------------------------------------------------------------------
// combine: out[n] += sum_k g_y[pmap[n,k]]
// ---------------------------------------------------------------------------
__global__ void combine_kernel(float* __restrict__ out) {
    const int n = blockIdx.x, t = threadIdx.x;
    __shared__ int pm[KSEL];
    if (t < KSEL) pm[t] = g_pmap[n * KSEL + t];
    __syncthreads();
    float4 acc = *(const float4*)(out + (size_t)n * D_DIM + t * 4);
#pragma unroll
    for (int k = 0; k < KSEL; k++) {
        float4 v = *(const float4*)(g_y + (size_t)pm[k] * D_DIM + t * 4);
        acc.x += v.x; acc.y += v.y; acc.z += v.z; acc.w += v.w;
    }
    *(float4*)(out + (size_t)n * D_DIM + t * 4) = acc;
}

// ---------------------------------------------------------------------------
// Launch
// ---------------------------------------------------------------------------
extern "C" void kernel_launch(void* const* d_in, const int* in_sizes, int n_in,
                              void* d_out, int out_size) {
    (void)in_sizes; (void)n_in; (void)out_size;
    const float* x       = (const float*)d_in[0];
    const float* gate_w  = (const float*)d_in[1];
    const float* w_gate  = (const float*)d_in[2];
    const float* w_up    = (const float*)d_in[3];
    const float* w_down  = (const float*)d_in[4];
    const float* sw_gate = (const float*)d_in[5];
    const float* sw_up   = (const float*)d_in[6];
    const float* sw_down = (const float*)d_in[7];
    float* out = (float*)d_out;

    cudaFuncSetAttribute(mma_gemm<true, true>,   cudaFuncAttributeMaxDynamicSharedMemorySize, SMEM_BYTES);
    cudaFuncSetAttribute(mma_gemm<true, false>,  cudaFuncAttributeMaxDynamicSharedMemorySize, SMEM_BYTES);
    cudaFuncSetAttribute(mma_gemm<false, true>,  cudaFuncAttributeMaxDynamicSharedMemorySize, SMEM_BYTES);
    cudaFuncSetAttribute(mma_gemm<false, false>, cudaFuncAttributeMaxDynamicSharedMemorySize, SMEM_BYTES);

    __half* xt; __half* wguT; __half* wdT; __half* swguT; __half* swdT;
    __half* hbuf; __half* hsbuf; float* ybuf;
    cudaGetSymbolAddress((void**)&xt,    g_xt);
    cudaGetSymbolAddress((void**)&wguT,  g_wguT);
    cudaGetSymbolAddress((void**)&wdT,   g_wdT);
    cudaGetSymbolAddress((void**)&swguT, g_swguT);
    cudaGetSymbolAddress((void**)&swdT,  g_swdT);
    cudaGetSymbolAddress((void**)&hbuf,  g_h);
    cudaGetSymbolAddress((void**)&hsbuf, g_hs);
    cudaGetSymbolAddress((void**)&ybuf,  g_y);

    gwnorm_kernel<<<E_NUM, 256>>>(gate_w);
    gating_kernel<<<NTOK, 256>>>(x);
    scatter_kernel<<<(NK + 255) / 256, 256>>>();

    prep_kernel<<<dim3(32, 32, 51), dim3(32, 8)>>>(
        w_gate, w_up, w_down, sw_gate, sw_up, sw_down, wguT, wdT, swguT, swdT);

    // shared expert (initializes out)
    mma_gemm<false, true><<<dim3(NTOK / 128, 8, 1), 256, SMEM_BYTES>>>(xt, swguT, hsbuf, nullptr);
    mma_gemm<false, false><<<dim3(NTOK / 128, 8, 1), 256, SMEM_BYTES>>>(hsbuf, swdT, nullptr, out);

    // routed experts
    mma_gemm<true, true><<<dim3(NTOK / 128, 8, E_NUM), 256, SMEM_BYTES>>>(xt, wguT, hbuf, nullptr);
    mma_gemm<true, false><<<dim3(NTOK / 128, 8, E_NUM), 256, SMEM_BYTES>>>(hbuf, wdT, nullptr, ybuf);

    combine_kernel<<<NTOK, 256>>>(out);
}

// round 8
// speedup vs baseline: 1.6824x; 1.0379x over previous
#include <cuda_runtime.h>
#include <cuda_fp16.h>
#include <cstdint>
#include <math.h>

#define D_DIM 1024
#define H_DIM 512
#define E_NUM 16
#define NTOK  4096
#define KSEL  8
#define NK    (NTOK * KSEL)

// ---------------------------------------------------------------------------
// Device scratch
// ---------------------------------------------------------------------------
__device__ float g_gwn[E_NUM * D_DIM];
__device__ int   g_idx[NK];
__device__ float g_w[NK];
__device__ int   g_cnt[E_NUM];
__device__ int   g_pos[E_NUM];
__device__ int   g_tok[NK + 128];
__device__ float g_tw[NK + 128];
__device__ int   g_pmap[NK];

__device__ __half g_xt[(size_t)NTOK * D_DIM];                // fp16 x
__device__ __half g_wguT[(size_t)E_NUM * 2 * H_DIM * D_DIM]; // [E][2H][D] interleaved gate/up
__device__ __half g_wdT [(size_t)E_NUM * D_DIM * H_DIM];     // [E][D][H]
__device__ __half g_swguT[(size_t)2 * H_DIM * D_DIM];
__device__ __half g_swdT [(size_t)D_DIM * H_DIM];

__device__ __half g_h [((size_t)NK + 128) * H_DIM];          // routed hidden (weighted)
__device__ __half g_hs[(size_t)NTOK * H_DIM];                // shared hidden
__device__ __half g_yh[(size_t)NK * D_DIM];                  // routed down output (fp16)

// ---------------------------------------------------------------------------
// Helpers (sm_80-compatible PTX only — harness compiles for plain sm_100)
// ---------------------------------------------------------------------------
__device__ __forceinline__ uint32_t smem_u32(const void* p) {
    uint32_t a;
    asm("{ .reg .u64 t; cvta.to.shared.u64 t, %1; cvt.u32.u64 %0, t; }" : "=r"(a) : "l"(p));
    return a;
}
__device__ __forceinline__ void cp16(uint32_t dst, const void* src) {
    asm volatile("cp.async.cg.shared.global [%0], [%1], 16;" :: "r"(dst), "l"(src));
}
#define CP_COMMIT() asm volatile("cp.async.commit_group;" ::: "memory")
#define CP_WAIT1()  asm volatile("cp.async.wait_group 1;" ::: "memory")

__device__ __forceinline__ void ldm4(uint32_t& r0, uint32_t& r1, uint32_t& r2, uint32_t& r3,
                                     uint32_t a) {
    asm volatile("ldmatrix.sync.aligned.m8n8.x4.shared.b16 {%0,%1,%2,%3}, [%4];"
                 : "=r"(r0), "=r"(r1), "=r"(r2), "=r"(r3) : "r"(a));
}
__device__ __forceinline__ void mma16(float* c, const uint32_t* a, uint32_t b0, uint32_t b1) {
    asm volatile("mma.sync.aligned.m16n8k16.row.col.f32.f16.f16.f32 "
                 "{%0,%1,%2,%3}, {%4,%5,%6,%7}, {%8,%9}, {%0,%1,%2,%3};"
                 : "+f"(c[0]), "+f"(c[1]), "+f"(c[2]), "+f"(c[3])
                 : "r"(a[0]), "r"(a[1]), "r"(a[2]), "r"(a[3]), "r"(b0), "r"(b1));
}

// ---------------------------------------------------------------------------
// Gating path (exact fp32 — must match reference routing)
// ---------------------------------------------------------------------------
__global__ void gwnorm_kernel(const float* __restrict__ gw) {
    int e = blockIdx.x, t = threadIdx.x;
    if (e == 0 && t < E_NUM) { g_cnt[t] = 0; g_pos[t] = 0; }
    __shared__ float red[8];
    float ss = 0.f;
    for (int i = t; i < D_DIM; i += 256) { float v = gw[e * D_DIM + i]; ss += v * v; }
    for (int o = 16; o; o >>= 1) ss += __shfl_down_sync(0xFFFFFFFFu, ss, o);
    if ((t & 31) == 0) red[t >> 5] = ss;
    __syncthreads();
    __shared__ float s_inv;
    if (t == 0) {
        float tot = 0.f;
        for (int i = 0; i < 8; i++) tot += red[i];
        s_inv = 1.0f / fmaxf(sqrtf(tot), 1e-12f);
    }
    __syncthreads();
    float inv = s_inv;
    for (int i = t; i < D_DIM; i += 256) g_gwn[e * D_DIM + i] = gw[e * D_DIM + i] * inv;
}

// Also emits the fp16 copy of x (g_xt).
__global__ void gating_kernel(const float* __restrict__ x) {
    int n = blockIdx.x, t = threadIdx.x;
    int warp = t >> 5, lane = t & 31;
    __shared__ float sx[D_DIM];
    __shared__ float red[8];
    __shared__ float slog[E_NUM];
    const float* xr = x + (size_t)n * D_DIM;
    float ss = 0.f;
    for (int i = t; i < D_DIM; i += 256) { float v = xr[i]; sx[i] = v; ss += v * v; }
    for (int o = 16; o; o >>= 1) ss += __shfl_down_sync(0xFFFFFFFFu, ss, o);
    if (lane == 0) red[warp] = ss;
    __syncthreads();
    for (int i = t; i < D_DIM; i += 256) g_xt[(size_t)n * D_DIM + i] = __float2half_rn(sx[i]);
    for (int j = 0; j < 2; j++) {
        int e = warp * 2 + j;
        const float* g = g_gwn + e * D_DIM;
        float d = 0.f;
        for (int i = lane; i < D_DIM; i += 32) d += sx[i] * g[i];
        for (int o = 16; o; o >>= 1) d += __shfl_down_sync(0xFFFFFFFFu, d, o);
        if (lane == 0) slog[e] = d;
    }
    __syncthreads();
    if (t == 0) {
        float ssq = 0.f;
        for (int i = 0; i < 8; i++) ssq += red[i];
        float inv = 1.0f / fmaxf(sqrtf(ssq), 1e-12f);
        float sc[E_NUM];
        for (int e = 0; e < E_NUM; e++) sc[e] = slog[e] * inv;
        int sel[KSEL]; float sw[KSEL]; float wsum = 0.f;
        for (int k = 0; k < KSEL; k++) {
            int bi = 0; float bv = -1e30f;
            for (int e = 0; e < E_NUM; e++)
                if (sc[e] > bv) { bv = sc[e]; bi = e; }
            sel[k] = bi;
            float s = 1.0f / (1.0f + __expf(-bv));
            sw[k] = s; wsum += s; sc[bi] = -1e30f;
        }
        float invw = 1.0f / wsum;
        for (int k = 0; k < KSEL; k++) {
            g_idx[n * KSEL + k] = sel[k];
            g_w[n * KSEL + k]   = sw[k] * invw;
            atomicAdd(&g_cnt[sel[k]], 1);
        }
    }
}

// scatter with in-block prefix over g_cnt
__global__ void scatter_kernel() {
    __shared__ int soff[E_NUM];
    int t = threadIdx.x;
    if (t == 0) {
        int a = 0;
        for (int e = 0; e < E_NUM; e++) { soff[e] = a; a += g_cnt[e]; }
    }
    __syncthreads();
    int id = blockIdx.x * 256 + t;
    if (id < NK) {
        int e = g_idx[id];
        int p = soff[e] + atomicAdd(&g_pos[e], 1);
        g_tok[p] = id / KSEL;
        g_tw[p]  = g_w[id];
        g_pmap[id] = p;
    }
}

// ---------------------------------------------------------------------------
// Fused weight prep: all 6 transposes (+fp16 convert, +gate/up interleave).
// ---------------------------------------------------------------------------
__global__ void prep_kernel(const float* __restrict__ wg, const float* __restrict__ wu,
                            const float* __restrict__ wd, const float* __restrict__ swg,
                            const float* __restrict__ swu, const float* __restrict__ swd,
                            __half* __restrict__ wguT, __half* __restrict__ wdT,
                            __half* __restrict__ swguT, __half* __restrict__ swdT) {
    int z = blockIdx.z;
    const float* src; __half* dst;
    int R, C, mul, add;
    size_t bi, bo;
    if (z < 16)       { int e = z;      src = wg;  dst = wguT;  R = D_DIM; C = H_DIM; mul = 2; add = 0; bi = (size_t)e * R * C; bo = bi * 2; }
    else if (z < 32)  { int e = z - 16; src = wu;  dst = wguT;  R = D_DIM; C = H_DIM; mul = 2; add = 1; bi = (size_t)e * R * C; bo = bi * 2; }
    else if (z < 48)  { int e = z - 32; src = wd;  dst = wdT;   R = H_DIM; C = D_DIM; mul = 1; add = 0; bi = (size_t)e * R * C; bo = bi; }
    else if (z == 48) { src = swg; dst = swguT; R = D_DIM; C = H_DIM; mul = 2; add = 0; bi = 0; bo = 0; }
    else if (z == 49) { src = swu; dst = swguT; R = D_DIM; C = H_DIM; mul = 2; add = 1; bi = 0; bo = 0; }
    else              { src = swd; dst = swdT;  R = H_DIM; C = D_DIM; mul = 1; add = 0; bi = 0; bo = 0; }

    int c0 = blockIdx.x * 32, r0 = blockIdx.y * 32;
    if (c0 >= C || r0 >= R) return;

    __shared__ float tile[32][33];
    int tx = threadIdx.x, ty = threadIdx.y;
#pragma unroll
    for (int j = 0; j < 32; j += 8)
        tile[ty + j][tx] = src[bi + (size_t)(r0 + ty + j) * C + c0 + tx];
    __syncthreads();
#pragma unroll
    for (int j = 0; j < 32; j += 8)
        dst[bo + (size_t)((c0 + ty + j) * mul + add) * R + r0 + tx] = __float2half_rn(tile[tx][ty + j]);
}

// ---------------------------------------------------------------------------
// fp16 mma.sync GEMM, merged routed+shared launch (z<16 routed expert z,
// z==16 shared). Block 128x128, BK=64, warp grid 2x4, m16n8k16, 3-stage.
// ---------------------------------------------------------------------------
#define ROWB    144
#define TILE_HB (128 * ROWB)
#define NSTG    3
#define SMEM_BYTES (2 * NSTG * TILE_HB + 1024)

template <bool GU>
__global__ void __launch_bounds__(256, 2)
mma_gemm(const __half* __restrict__ Art, const __half* __restrict__ Ash,
         const __half* __restrict__ Brt, const __half* __restrict__ Bsh,
         __half* __restrict__ outRt, void* __restrict__ outShv) {
    constexpr int KD = GU ? D_DIM : H_DIM;
    const int e = blockIdx.z;
    const bool gather = (e < E_NUM);
    const int cnt = gather ? g_cnt[e] : NTOK;
    const int m0  = blockIdx.x * 128;
    if (m0 >= cnt) return;
    int offr = 0;
    if (gather) {
        for (int q = 0; q < E_NUM; q++) offr += (q < e) ? g_cnt[q] : 0;
    }
    const int n0 = blockIdx.y * 128;

    const __half* A = gather ? Art : Ash;
    const __half* B = gather ? (Brt + (size_t)e * 1024 * KD) : Bsh;

    extern __shared__ char smc[];
    const uint32_t uA = smem_u32(smc);
    const uint32_t uB = uA + NSTG * TILE_HB;
    int*   rtok = (int*)(smc + 2 * NSTG * TILE_HB);
    float* twsh = (float*)(smc + 2 * NSTG * TILE_HB + 512);

    const int t = threadIdx.x;
    const int warp = t >> 5, lane = t & 31;
    const int wm = warp >> 2, wn = warp & 3;

    if (t < 128) {
        int gm = m0 + t;
        int cg = (gm < cnt) ? gm : 0;
        int src;
        if (GU) src = gather ? g_tok[offr + cg] : gm;
        else    src = gather ? (offr + gm) : gm;
        rtok[t] = src;
        twsh[t] = (GU && gather) ? g_tw[offr + cg] : 1.0f;
    }
    __syncthreads();

    const __half* aP[4];
    const __half* bP[4];
    uint32_t sOff[4];
#pragma unroll
    for (int j = 0; j < 4; j++) {
        int cidx = t + j * 256;
        int row = cidx >> 3, kc = cidx & 7;
        aP[j] = A + (size_t)rtok[row] * KD + kc * 8;
        bP[j] = B + (size_t)(n0 + row) * KD + kc * 8;
        sOff[j] = (uint32_t)(row * ROWB + kc * 16);
    }

#define LOADSTAGE(s, k0) do {                                       \
        _Pragma("unroll")                                           \
        for (int j = 0; j < 4; j++) {                               \
            cp16(uA + (s) * TILE_HB + sOff[j], aP[j] + (k0));       \
            cp16(uB + (s) * TILE_HB + sOff[j], bP[j] + (k0));       \
        }                                                           \
    } while (0)

    float c[4][4][4] = {};

    const int NIT = KD / 64;
    LOADSTAGE(0, 0);  CP_COMMIT();
    LOADSTAGE(1, 64); CP_COMMIT();

    for (int i = 0; i < NIT; i++) {
        CP_WAIT1();
        __syncthreads();
        const int ld = i + 2;
        if (ld < NIT) LOADSTAGE(ld % NSTG, ld * 64);
        CP_COMMIT();

        const int s = i % NSTG;
        const uint32_t uAs = uA + s * TILE_HB;
        const uint32_t uBs = uB + s * TILE_HB;
#pragma unroll
        for (int ks = 0; ks < 4; ks++) {
            uint32_t a[4][4], b[2][4];
#pragma unroll
            for (int mt = 0; mt < 4; mt++) {
                uint32_t row = wm * 64 + mt * 16 + (lane & 7) + ((lane >> 3) & 1) * 8;
                uint32_t ad = uAs + row * ROWB + ks * 32 + (lane >> 4) * 16;
                ldm4(a[mt][0], a[mt][1], a[mt][2], a[mt][3], ad);
            }
#pragma unroll
            for (int p = 0; p < 2; p++) {
                uint32_t row = wn * 32 + p * 16 + ((lane >> 4) & 1) * 8 + (lane & 7);
                uint32_t ad = uBs + row * ROWB + ks * 32 + ((lane >> 3) & 1) * 16;
                ldm4(b[p][0], b[p][1], b[p][2], b[p][3], ad);
            }
#pragma unroll
            for (int mt = 0; mt < 4; mt++) {
#pragma unroll
                for (int nt = 0; nt < 4; nt++)
                    mma16(c[mt][nt], a[mt], b[nt >> 1][2 * (nt & 1)], b[nt >> 1][2 * (nt & 1) + 1]);
            }
        }
    }
#undef LOADSTAGE

#pragma unroll
    for (int mt = 0; mt < 4; mt++) {
        int r0 = wm * 64 + mt * 16 + (lane >> 2);
#pragma unroll
        for (int pass = 0; pass < 2; pass++) {
            int r = r0 + pass * 8;
            int gm = m0 + r;
            if (gm < cnt) {
                if (GU) {
                    // hidden output (fp16): routed -> g_h rows offr+gm, shared -> g_hs rows gm
                    float tw = twsh[r];
                    __half* orow = (gather ? outRt + (size_t)(offr + gm) * H_DIM
                                           : (__half*)outShv + (size_t)gm * H_DIM);
#pragma unroll
                    for (int nt = 0; nt < 4; nt++) {
                        float g = c[mt][nt][pass * 2];
                        float u = c[mt][nt][pass * 2 + 1];
                        int h = (n0 + wn * 32 + nt * 8) / 2 + (lane & 3);
                        orow[h] = __float2half_rn(tw * u * g / (1.0f + __expf(-g)));
                    }
                } else if (gather) {
                    // routed down output (fp16 half2 stores)
                    __half* orow = outRt + (size_t)(offr + gm) * D_DIM;
#pragma unroll
                    for (int nt = 0; nt < 4; nt++) {
                        int n = n0 + wn * 32 + nt * 8 + 2 * (lane & 3);
                        *(__half2*)(orow + n) =
                            __floats2half2_rn(c[mt][nt][pass * 2], c[mt][nt][pass * 2 + 1]);
                    }
                } else {
                    // shared down output (fp32, initializes d_out)
                    float* orow = (float*)outShv + (size_t)gm * D_DIM;
#pragma unroll
                    for (int nt = 0; nt < 4; nt++) {
                        int n = n0 + wn * 32 + nt * 8 + 2 * (lane & 3);
                        *(float2*)(orow + n) =
                            make_float2(c[mt][nt][pass * 2], c[mt][nt][pass * 2 + 1]);
                    }
                }
            }
        }
    }
}

// ---------------------------------------------------------------------------
// combine: out[n] (shared result) += sum_k g_yh[pmap[n,k]]  (fp16 reads)
// ---------------------------------------------------------------------------
__global__ void combine_kernel(float* __restrict__ out) {
    const int n = blockIdx.x, t = threadIdx.x;
    __shared__ int pm[KSEL];
    if (t < KSEL) pm[t] = g_pmap[n * KSEL + t];
    __syncthreads();
    float4 acc = *(const float4*)(out + (size_t)n * D_DIM + t * 4);
#pragma unroll
    for (int k = 0; k < KSEL; k++) {
        const __half2* p = (const __half2*)(g_yh + (size_t)pm[k] * D_DIM + t * 4);
        float2 v0 = __half22float2(p[0]);
        float2 v1 = __half22float2(p[1]);
        acc.x += v0.x; acc.y += v0.y; acc.z += v1.x; acc.w += v1.y;
    }
    *(float4*)(out + (size_t)n * D_DIM + t * 4) = acc;
}

// ---------------------------------------------------------------------------
// Launch
// ---------------------------------------------------------------------------
extern "C" void kernel_launch(void* const* d_in, const int* in_sizes, int n_in,
                              void* d_out, int out_size) {
    (void)in_sizes; (void)n_in; (void)out_size;
    const float* x       = (const float*)d_in[0];
    const float* gate_w  = (const float*)d_in[1];
    const float* w_gate  = (const float*)d_in[2];
    const float* w_up    = (const float*)d_in[3];
    const float* w_down  = (const float*)d_in[4];
    const float* sw_gate = (const float*)d_in[5];
    const float* sw_up   = (const float*)d_in[6];
    const float* sw_down = (const float*)d_in[7];
    float* out = (float*)d_out;

    cudaFuncSetAttribute(mma_gemm<true>,  cudaFuncAttributeMaxDynamicSharedMemorySize, SMEM_BYTES);
    cudaFuncSetAttribute(mma_gemm<false>, cudaFuncAttributeMaxDynamicSharedMemorySize, SMEM_BYTES);

    __half* xt; __half* wguT; __half* wdT; __half* swguT; __half* swdT;
    __half* hbuf; __half* hsbuf; __half* ybuf;
    cudaGetSymbolAddress((void**)&xt,    g_xt);
    cudaGetSymbolAddress((void**)&wguT,  g_wguT);
    cudaGetSymbolAddress((void**)&wdT,   g_wdT);
    cudaGetSymbolAddress((void**)&swguT, g_swguT);
    cudaGetSymbolAddress((void**)&swdT,  g_swdT);
    cudaGetSymbolAddress((void**)&hbuf,  g_h);
    cudaGetSymbolAddress((void**)&hsbuf, g_hs);
    cudaGetSymbolAddress((void**)&ybuf,  g_yh);

    gwnorm_kernel<<<E_NUM, 256>>>(gate_w);
    gating_kernel<<<NTOK, 256>>>(x);
    scatter_kernel<<<(NK + 255) / 256, 256>>>();

    prep_kernel<<<dim3(32, 32, 51), dim3(32, 8)>>>(
        w_gate, w_up, w_down, sw_gate, sw_up, sw_down, wguT, wdT, swguT, swdT);

    // GU: routed (z<16) + shared (z==16) in one launch
    mma_gemm<true><<<dim3(32, 8, E_NUM + 1), 256, SMEM_BYTES>>>(
        xt, xt, wguT, swguT, hbuf, (void*)hsbuf);

    // DN: routed -> g_yh (fp16), shared -> out (fp32)
    mma_gemm<false><<<dim3(32, 8, E_NUM + 1), 256, SMEM_BYTES>>>(
        hbuf, hsbuf, wdT, swdT, ybuf, (void*)out);

    combine_kernel<<<NTOK, 256>>>(out);
}

// round 9
// speedup vs baseline: 1.7265x; 1.0262x over previous
#include <cuda_runtime.h>
#include <cuda_fp16.h>
#include <cstdint>
#include <math.h>

#define D_DIM 1024
#define H_DIM 512
#define E_NUM 16
#define NTOK  4096
#define KSEL  8
#define NK    (NTOK * KSEL)

// ---------------------------------------------------------------------------
// Device scratch
// ---------------------------------------------------------------------------
__device__ float g_gwn[E_NUM * D_DIM];
__device__ int   g_idx[NK];
__device__ float g_w[NK];
__device__ int   g_cnt[E_NUM];
__device__ int   g_pos[E_NUM];
__device__ int   g_tok[NK + 128];
__device__ float g_tw[NK + 128];
__device__ int   g_pmap[NK];

__device__ __half g_xt[(size_t)NTOK * D_DIM];                // fp16 x
__device__ __half g_wguT[(size_t)E_NUM * 2 * H_DIM * D_DIM]; // [E][2H][D] interleaved gate/up
__device__ __half g_wdT [(size_t)E_NUM * D_DIM * H_DIM];     // [E][D][H]
__device__ __half g_swguT[(size_t)2 * H_DIM * D_DIM];
__device__ __half g_swdT [(size_t)D_DIM * H_DIM];

__device__ __half g_h [((size_t)NK + 128) * H_DIM];          // routed hidden (weighted)
__device__ __half g_hs[(size_t)NTOK * H_DIM];                // shared hidden
__device__ __half g_yh[(size_t)NK * D_DIM];                  // routed down output (fp16)

// ---------------------------------------------------------------------------
// Helpers (sm_80-compatible PTX only — harness compiles for plain sm_100)
// ---------------------------------------------------------------------------
__device__ __forceinline__ uint32_t smem_u32(const void* p) {
    uint32_t a;
    asm("{ .reg .u64 t; cvta.to.shared.u64 t, %1; cvt.u32.u64 %0, t; }" : "=r"(a) : "l"(p));
    return a;
}
__device__ __forceinline__ void cp16(uint32_t dst, const void* src) {
    asm volatile("cp.async.cg.shared.global [%0], [%1], 16;" :: "r"(dst), "l"(src));
}
#define CP_COMMIT() asm volatile("cp.async.commit_group;" ::: "memory")
#define CP_WAIT1()  asm volatile("cp.async.wait_group 1;" ::: "memory")

__device__ __forceinline__ void ldm4(uint32_t& r0, uint32_t& r1, uint32_t& r2, uint32_t& r3,
                                     uint32_t a) {
    asm volatile("ldmatrix.sync.aligned.m8n8.x4.shared.b16 {%0,%1,%2,%3}, [%4];"
                 : "=r"(r0), "=r"(r1), "=r"(r2), "=r"(r3) : "r"(a));
}
__device__ __forceinline__ void mma16(float* c, const uint32_t* a, uint32_t b0, uint32_t b1) {
    asm volatile("mma.sync.aligned.m16n8k16.row.col.f32.f16.f16.f32 "
                 "{%0,%1,%2,%3}, {%4,%5,%6,%7}, {%8,%9}, {%0,%1,%2,%3};"
                 : "+f"(c[0]), "+f"(c[1]), "+f"(c[2]), "+f"(c[3])
                 : "r"(a[0]), "r"(a[1]), "r"(a[2]), "r"(a[3]), "r"(b0), "r"(b1));
}

// ---------------------------------------------------------------------------
// prep2: fused weight transposes (+fp16, +gate/up interleave) AND gwnorm.
// grid (32, 16, 52), block (32, 8).
//   z < 51 : transpose-convert jobs, 64r x 32c tiles, half2 stores
//   z == 51: blocks (x<16, y==0) run gwnorm for expert x (exact fp32)
// ---------------------------------------------------------------------------
__global__ void prep2_kernel(const float* __restrict__ gw,
                             const float* __restrict__ wg, const float* __restrict__ wu,
                             const float* __restrict__ wd, const float* __restrict__ swg,
                             const float* __restrict__ swu, const float* __restrict__ swd,
                             __half* __restrict__ wguT, __half* __restrict__ wdT,
                             __half* __restrict__ swguT, __half* __restrict__ swdT) {
    const int z = blockIdx.z;
    const int tx = threadIdx.x, ty = threadIdx.y;

    if (z == 51) {
        // ---- gwnorm (exact fp32, matches reference routing) ----
        if (blockIdx.y != 0 || blockIdx.x >= E_NUM) return;
        const int e = blockIdx.x;
        const int t = ty * 32 + tx;
        if (e == 0 && t < E_NUM) { g_cnt[t] = 0; g_pos[t] = 0; }
        __shared__ float red[8];
        float ss = 0.f;
        for (int i = t; i < D_DIM; i += 256) { float v = gw[e * D_DIM + i]; ss += v * v; }
        for (int o = 16; o; o >>= 1) ss += __shfl_down_sync(0xFFFFFFFFu, ss, o);
        if ((t & 31) == 0) red[t >> 5] = ss;
        __syncthreads();
        __shared__ float s_inv;
        if (t == 0) {
            float tot = 0.f;
            for (int i = 0; i < 8; i++) tot += red[i];
            s_inv = 1.0f / fmaxf(sqrtf(tot), 1e-12f);
        }
        __syncthreads();
        float inv = s_inv;
        for (int i = t; i < D_DIM; i += 256) g_gwn[e * D_DIM + i] = gw[e * D_DIM + i] * inv;
        return;
    }

    // ---- transpose-convert job ----
    const float* src; __half* dst;
    int R, C, mul, add;
    size_t bi, bo;
    if (z < 16)       { int e = z;      src = wg;  dst = wguT;  R = D_DIM; C = H_DIM; mul = 2; add = 0; bi = (size_t)e * R * C; bo = bi * 2; }
    else if (z < 32)  { int e = z - 16; src = wu;  dst = wguT;  R = D_DIM; C = H_DIM; mul = 2; add = 1; bi = (size_t)e * R * C; bo = bi * 2; }
    else if (z < 48)  { int e = z - 32; src = wd;  dst = wdT;   R = H_DIM; C = D_DIM; mul = 1; add = 0; bi = (size_t)e * R * C; bo = bi; }
    else if (z == 48) { src = swg; dst = swguT; R = D_DIM; C = H_DIM; mul = 2; add = 0; bi = 0; bo = 0; }
    else if (z == 49) { src = swu; dst = swguT; R = D_DIM; C = H_DIM; mul = 2; add = 1; bi = 0; bo = 0; }
    else              { src = swd; dst = swdT;  R = H_DIM; C = D_DIM; mul = 1; add = 0; bi = 0; bo = 0; }

    const int c0 = blockIdx.x * 32, r0 = blockIdx.y * 64;
    if (c0 >= C || r0 >= R) return;

    __shared__ float tile[32][65];   // [c][r], pad avoids bank conflicts
    // read: src rows r0..r0+63, cols c0..c0+31 (coalesced 128B per warp-row)
#pragma unroll
    for (int j = 0; j < 64; j += 8)
        tile[tx][ty + j] = src[bi + (size_t)(r0 + ty + j) * C + c0 + tx];
    __syncthreads();
    // write: dst row (c0+c)*mul+add, 64 halves starting at r0 (half2 per lane, 128B/warp)
#pragma unroll
    for (int jc = 0; jc < 4; jc++) {
        int c = ty + jc * 8;
        __half2 v = __floats2half2_rn(tile[c][2 * tx], tile[c][2 * tx + 1]);
        *(__half2*)(dst + bo + (size_t)((c0 + c) * mul + add) * R + r0 + 2 * tx) = v;
    }
}

// ---------------------------------------------------------------------------
// Gating (exact fp32). Also emits the fp16 copy of x (g_xt).
// ---------------------------------------------------------------------------
__global__ void gating_kernel(const float* __restrict__ x) {
    int n = blockIdx.x, t = threadIdx.x;
    int warp = t >> 5, lane = t & 31;
    __shared__ float sx[D_DIM];
    __shared__ float red[8];
    __shared__ float slog[E_NUM];
    const float* xr = x + (size_t)n * D_DIM;
    float ss = 0.f;
    for (int i = t; i < D_DIM; i += 256) { float v = xr[i]; sx[i] = v; ss += v * v; }
    for (int o = 16; o; o >>= 1) ss += __shfl_down_sync(0xFFFFFFFFu, ss, o);
    if (lane == 0) red[warp] = ss;
    __syncthreads();
    for (int i = t; i < D_DIM; i += 256) g_xt[(size_t)n * D_DIM + i] = __float2half_rn(sx[i]);
    for (int j = 0; j < 2; j++) {
        int e = warp * 2 + j;
        const float* g = g_gwn + e * D_DIM;
        float d = 0.f;
        for (int i = lane; i < D_DIM; i += 32) d += sx[i] * g[i];
        for (int o = 16; o; o >>= 1) d += __shfl_down_sync(0xFFFFFFFFu, d, o);
        if (lane == 0) slog[e] = d;
    }
    __syncthreads();
    if (t == 0) {
        float ssq = 0.f;
        for (int i = 0; i < 8; i++) ssq += red[i];
        float inv = 1.0f / fmaxf(sqrtf(ssq), 1e-12f);
        float sc[E_NUM];
        for (int e = 0; e < E_NUM; e++) sc[e] = slog[e] * inv;
        int sel[KSEL]; float sw[KSEL]; float wsum = 0.f;
        for (int k = 0; k < KSEL; k++) {
            int bi = 0; float bv = -1e30f;
            for (int e = 0; e < E_NUM; e++)
                if (sc[e] > bv) { bv = sc[e]; bi = e; }
            sel[k] = bi;
            float s = 1.0f / (1.0f + __expf(-bv));
            sw[k] = s; wsum += s; sc[bi] = -1e30f;
        }
        float invw = 1.0f / wsum;
        for (int k = 0; k < KSEL; k++) {
            g_idx[n * KSEL + k] = sel[k];
            g_w[n * KSEL + k]   = sw[k] * invw;
            atomicAdd(&g_cnt[sel[k]], 1);
        }
    }
}

// scatter with in-block prefix over g_cnt
__global__ void scatter_kernel() {
    __shared__ int soff[E_NUM];
    int t = threadIdx.x;
    if (t == 0) {
        int a = 0;
        for (int e = 0; e < E_NUM; e++) { soff[e] = a; a += g_cnt[e]; }
    }
    __syncthreads();
    int id = blockIdx.x * 256 + t;
    if (id < NK) {
        int e = g_idx[id];
        int p = soff[e] + atomicAdd(&g_pos[e], 1);
        g_tok[p] = id / KSEL;
        g_tw[p]  = g_w[id];
        g_pmap[id] = p;
    }
}

// ---------------------------------------------------------------------------
// fp16 mma.sync GEMM, merged routed+shared launch (z<16 routed expert z,
// z==16 shared). Block 128x128, BK=64, warp grid 2x4, m16n8k16, 3-stage.
// ---------------------------------------------------------------------------
#define ROWB    144
#define TILE_HB (128 * ROWB)
#define NSTG    3
#define SMEM_BYTES (2 * NSTG * TILE_HB + 1024)

template <bool GU>
__global__ void __launch_bounds__(256, 2)
mma_gemm(const __half* __restrict__ Art, const __half* __restrict__ Ash,
         const __half* __restrict__ Brt, const __half* __restrict__ Bsh,
         __half* __restrict__ outRt, void* __restrict__ outShv) {
    constexpr int KD = GU ? D_DIM : H_DIM;
    const int e = blockIdx.z;
    const bool gather = (e < E_NUM);
    const int cnt = gather ? g_cnt[e] : NTOK;
    const int m0  = blockIdx.x * 128;
    if (m0 >= cnt) return;
    int offr = 0;
    if (gather) {
        for (int q = 0; q < E_NUM; q++) offr += (q < e) ? g_cnt[q] : 0;
    }
    const int n0 = blockIdx.y * 128;

    const __half* A = gather ? Art : Ash;
    const __half* B = gather ? (Brt + (size_t)e * 1024 * KD) : Bsh;

    extern __shared__ char smc[];
    const uint32_t uA = smem_u32(smc);
    const uint32_t uB = uA + NSTG * TILE_HB;
    int*   rtok = (int*)(smc + 2 * NSTG * TILE_HB);
    float* twsh = (float*)(smc + 2 * NSTG * TILE_HB + 512);

    const int t = threadIdx.x;
    const int warp = t >> 5, lane = t & 31;
    const int wm = warp >> 2, wn = warp & 3;

    if (t < 128) {
        int gm = m0 + t;
        int cg = (gm < cnt) ? gm : 0;
        int src;
        if (GU) src = gather ? g_tok[offr + cg] : gm;
        else    src = gather ? (offr + gm) : gm;
        rtok[t] = src;
        twsh[t] = (GU && gather) ? g_tw[offr + cg] : 1.0f;
    }
    __syncthreads();

    const __half* aP[4];
    const __half* bP[4];
    uint32_t sOff[4];
#pragma unroll
    for (int j = 0; j < 4; j++) {
        int cidx = t + j * 256;
        int row = cidx >> 3, kc = cidx & 7;
        aP[j] = A + (size_t)rtok[row] * KD + kc * 8;
        bP[j] = B + (size_t)(n0 + row) * KD + kc * 8;
        sOff[j] = (uint32_t)(row * ROWB + kc * 16);
    }

#define LOADSTAGE(s, k0) do {                                       \
        _Pragma("unroll")                                           \
        for (int j = 0; j < 4; j++) {                               \
            cp16(uA + (s) * TILE_HB + sOff[j], aP[j] + (k0));       \
            cp16(uB + (s) * TILE_HB + sOff[j], bP[j] + (k0));       \
        }                                                           \
    } while (0)

    float c[4][4][4] = {};

    const int NIT = KD / 64;
    LOADSTAGE(0, 0);  CP_COMMIT();
    LOADSTAGE(1, 64); CP_COMMIT();

    for (int i = 0; i < NIT; i++) {
        CP_WAIT1();
        __syncthreads();
        const int ld = i + 2;
        if (ld < NIT) LOADSTAGE(ld % NSTG, ld * 64);
        CP_COMMIT();

        const int s = i % NSTG;
        const uint32_t uAs = uA + s * TILE_HB;
        const uint32_t uBs = uB + s * TILE_HB;
#pragma unroll
        for (int ks = 0; ks < 4; ks++) {
            uint32_t a[4][4], b[2][4];
#pragma unroll
            for (int mt = 0; mt < 4; mt++) {
                uint32_t row = wm * 64 + mt * 16 + (lane & 7) + ((lane >> 3) & 1) * 8;
                uint32_t ad = uAs + row * ROWB + ks * 32 + (lane >> 4) * 16;
                ldm4(a[mt][0], a[mt][1], a[mt][2], a[mt][3], ad);
            }
#pragma unroll
            for (int p = 0; p < 2; p++) {
                uint32_t row = wn * 32 + p * 16 + ((lane >> 4) & 1) * 8 + (lane & 7);
                uint32_t ad = uBs + row * ROWB + ks * 32 + ((lane >> 3) & 1) * 16;
                ldm4(b[p][0], b[p][1], b[p][2], b[p][3], ad);
            }
#pragma unroll
            for (int mt = 0; mt < 4; mt++) {
#pragma unroll
                for (int nt = 0; nt < 4; nt++)
                    mma16(c[mt][nt], a[mt], b[nt >> 1][2 * (nt & 1)], b[nt >> 1][2 * (nt & 1) + 1]);
            }
        }
    }
#undef LOADSTAGE

#pragma unroll
    for (int mt = 0; mt < 4; mt++) {
        int r0 = wm * 64 + mt * 16 + (lane >> 2);
#pragma unroll
        for (int pass = 0; pass < 2; pass++) {
            int r = r0 + pass * 8;
            int gm = m0 + r;
            if (gm < cnt) {
                if (GU) {
                    float tw = twsh[r];
                    __half* orow = (gather ? outRt + (size_t)(offr + gm) * H_DIM
                                           : (__half*)outShv + (size_t)gm * H_DIM);
#pragma unroll
                    for (int nt = 0; nt < 4; nt++) {
                        float g = c[mt][nt][pass * 2];
                        float u = c[mt][nt][pass * 2 + 1];
                        int h = (n0 + wn * 32 + nt * 8) / 2 + (lane & 3);
                        orow[h] = __float2half_rn(tw * u * g / (1.0f + __expf(-g)));
                    }
                } else if (gather) {
                    __half* orow = outRt + (size_t)(offr + gm) * D_DIM;
#pragma unroll
                    for (int nt = 0; nt < 4; nt++) {
                        int n = n0 + wn * 32 + nt * 8 + 2 * (lane & 3);
                        *(__half2*)(orow + n) =
                            __floats2half2_rn(c[mt][nt][pass * 2], c[mt][nt][pass * 2 + 1]);
                    }
                } else {
                    float* orow = (float*)outShv + (size_t)gm * D_DIM;
#pragma unroll
                    for (int nt = 0; nt < 4; nt++) {
                        int n = n0 + wn * 32 + nt * 8 + 2 * (lane & 3);
                        *(float2*)(orow + n) =
                            make_float2(c[mt][nt][pass * 2], c[mt][nt][pass * 2 + 1]);
                    }
                }
            }
        }
    }
}

// ---------------------------------------------------------------------------
// combine: out[n] (shared result) += sum_k g_yh[pmap[n,k]]  (fp16 reads)
// ---------------------------------------------------------------------------
__global__ void combine_kernel(float* __restrict__ out) {
    const int n = blockIdx.x, t = threadIdx.x;
    __shared__ int pm[KSEL];
    if (t < KSEL) pm[t] = g_pmap[n * KSEL + t];
    __syncthreads();
    float4 acc = *(const float4*)(out + (size_t)n * D_DIM + t * 4);
#pragma unroll
    for (int k = 0; k < KSEL; k++) {
        const __half2* p = (const __half2*)(g_yh + (size_t)pm[k] * D_DIM + t * 4);
        float2 v0 = __half22float2(p[0]);
        float2 v1 = __half22float2(p[1]);
        acc.x += v0.x; acc.y += v0.y; acc.z += v1.x; acc.w += v1.y;
    }
    *(float4*)(out + (size_t)n * D_DIM + t * 4) = acc;
}

// ---------------------------------------------------------------------------
// Launch:  prep2(1) gating(2) scatter(3) GU(4) DN(5) combine(6)
// ---------------------------------------------------------------------------
extern "C" void kernel_launch(void* const* d_in, const int* in_sizes, int n_in,
                              void* d_out, int out_size) {
    (void)in_sizes; (void)n_in; (void)out_size;
    const float* x       = (const float*)d_in[0];
    const float* gate_w  = (const float*)d_in[1];
    const float* w_gate  = (const float*)d_in[2];
    const float* w_up    = (const float*)d_in[3];
    const float* w_down  = (const float*)d_in[4];
    const float* sw_gate = (const float*)d_in[5];
    const float* sw_up   = (const float*)d_in[6];
    const float* sw_down = (const float*)d_in[7];
    float* out = (float*)d_out;

    cudaFuncSetAttribute(mma_gemm<true>,  cudaFuncAttributeMaxDynamicSharedMemorySize, SMEM_BYTES);
    cudaFuncSetAttribute(mma_gemm<false>, cudaFuncAttributeMaxDynamicSharedMemorySize, SMEM_BYTES);

    __half* xt; __half* wguT; __half* wdT; __half* swguT; __half* swdT;
    __half* hbuf; __half* hsbuf; __half* ybuf;
    cudaGetSymbolAddress((void**)&xt,    g_xt);
    cudaGetSymbolAddress((void**)&wguT,  g_wguT);
    cudaGetSymbolAddress((void**)&wdT,   g_wdT);
    cudaGetSymbolAddress((void**)&swguT, g_swguT);
    cudaGetSymbolAddress((void**)&swdT,  g_swdT);
    cudaGetSymbolAddress((void**)&hbuf,  g_h);
    cudaGetSymbolAddress((void**)&hsbuf, g_hs);
    cudaGetSymbolAddress((void**)&ybuf,  g_yh);

    prep2_kernel<<<dim3(32, 16, 52), dim3(32, 8)>>>(
        gate_w, w_gate, w_up, w_down, sw_gate, sw_up, sw_down, wguT, wdT, swguT, swdT);
    gating_kernel<<<NTOK, 256>>>(x);
    scatter_kernel<<<(NK + 255) / 256, 256>>>();

    // GU: routed (z<16) + shared (z==16) in one launch  -- capture slot 4
    mma_gemm<true><<<dim3(32, 8, E_NUM + 1), 256, SMEM_BYTES>>>(
        xt, xt, wguT, swguT, hbuf, (void*)hsbuf);

    // DN: routed -> g_yh (fp16), shared -> out (fp32)
    mma_gemm<false><<<dim3(32, 8, E_NUM + 1), 256, SMEM_BYTES>>>(
        hbuf, hsbuf, wdT, swdT, ybuf, (void*)out);

    combine_kernel<<<NTOK, 256>>>(out);
}

// round 10
// speedup vs baseline: 1.7333x; 1.0039x over previous
#include <cuda_runtime.h>
#include <cuda_fp16.h>
#include <cstdint>
#include <math.h>

#define D_DIM 1024
#define H_DIM 512
#define E_NUM 16
#define NTOK  4096
#define KSEL  8
#define NK    (NTOK * KSEL)

// ---------------------------------------------------------------------------
// Device scratch
// ---------------------------------------------------------------------------
__device__ float g_gwn[E_NUM * D_DIM];
__device__ int   g_idx[NK];
__device__ float g_w[NK];
__device__ int   g_cnt[E_NUM];
__device__ int   g_pos[E_NUM];
__device__ int   g_tok[NK + 128];
__device__ float g_tw[NK + 128];
__device__ int   g_pmap[NK];

__device__ __half g_xt[(size_t)NTOK * D_DIM];                // fp16 x
__device__ __half g_wguT[(size_t)E_NUM * 2 * H_DIM * D_DIM]; // [E][2H][D] interleaved gate/up
__device__ __half g_wdT [(size_t)E_NUM * D_DIM * H_DIM];     // [E][D][H]
__device__ __half g_swguT[(size_t)2 * H_DIM * D_DIM];
__device__ __half g_swdT [(size_t)D_DIM * H_DIM];

__device__ __half g_h [((size_t)NK + 128) * H_DIM];          // routed hidden (weighted)
__device__ __half g_hs[(size_t)NTOK * H_DIM];                // shared hidden
__device__ __half g_yh[(size_t)NK * D_DIM];                  // routed down output (fp16)

// ---------------------------------------------------------------------------
// Helpers (sm_80-compatible PTX only — harness compiles for plain sm_100)
// ---------------------------------------------------------------------------
__device__ __forceinline__ uint32_t smem_u32(const void* p) {
    uint32_t a;
    asm("{ .reg .u64 t; cvta.to.shared.u64 t, %1; cvt.u32.u64 %0, t; }" : "=r"(a) : "l"(p));
    return a;
}
__device__ __forceinline__ void cp16(uint32_t dst, const void* src) {
    asm volatile("cp.async.cg.shared.global [%0], [%1], 16;" :: "r"(dst), "l"(src));
}
#define CP_COMMIT() asm volatile("cp.async.commit_group;" ::: "memory")
#define CP_WAIT1()  asm volatile("cp.async.wait_group 1;" ::: "memory")

__device__ __forceinline__ void ldm4(uint32_t& r0, uint32_t& r1, uint32_t& r2, uint32_t& r3,
                                     uint32_t a) {
    asm volatile("ldmatrix.sync.aligned.m8n8.x4.shared.b16 {%0,%1,%2,%3}, [%4];"
                 : "=r"(r0), "=r"(r1), "=r"(r2), "=r"(r3) : "r"(a));
}
__device__ __forceinline__ void mma16(float* c, const uint32_t* a, uint32_t b0, uint32_t b1) {
    asm volatile("mma.sync.aligned.m16n8k16.row.col.f32.f16.f16.f32 "
                 "{%0,%1,%2,%3}, {%4,%5,%6,%7}, {%8,%9}, {%0,%1,%2,%3};"
                 : "+f"(c[0]), "+f"(c[1]), "+f"(c[2]), "+f"(c[3])
                 : "r"(a[0]), "r"(a[1]), "r"(a[2]), "r"(a[3]), "r"(b0), "r"(b1));
}

// ---------------------------------------------------------------------------
// prep2: fused weight transposes (+fp16, +gate/up interleave) AND gwnorm.
// grid (32, 16, 52), block (32, 8).
// ---------------------------------------------------------------------------
__global__ void prep2_kernel(const float* __restrict__ gw,
                             const float* __restrict__ wg, const float* __restrict__ wu,
                             const float* __restrict__ wd, const float* __restrict__ swg,
                             const float* __restrict__ swu, const float* __restrict__ swd,
                             __half* __restrict__ wguT, __half* __restrict__ wdT,
                             __half* __restrict__ swguT, __half* __restrict__ swdT) {
    const int z = blockIdx.z;
    const int tx = threadIdx.x, ty = threadIdx.y;

    if (z == 51) {
        if (blockIdx.y != 0 || blockIdx.x >= E_NUM) return;
        const int e = blockIdx.x;
        const int t = ty * 32 + tx;
        if (e == 0 && t < E_NUM) { g_cnt[t] = 0; g_pos[t] = 0; }
        __shared__ float red[8];
        float ss = 0.f;
        for (int i = t; i < D_DIM; i += 256) { float v = gw[e * D_DIM + i]; ss += v * v; }
        for (int o = 16; o; o >>= 1) ss += __shfl_down_sync(0xFFFFFFFFu, ss, o);
        if ((t & 31) == 0) red[t >> 5] = ss;
        __syncthreads();
        __shared__ float s_inv;
        if (t == 0) {
            float tot = 0.f;
            for (int i = 0; i < 8; i++) tot += red[i];
            s_inv = 1.0f / fmaxf(sqrtf(tot), 1e-12f);
        }
        __syncthreads();
        float inv = s_inv;
        for (int i = t; i < D_DIM; i += 256) g_gwn[e * D_DIM + i] = gw[e * D_DIM + i] * inv;
        return;
    }

    const float* src; __half* dst;
    int R, C, mul, add;
    size_t bi, bo;
    if (z < 16)       { int e = z;      src = wg;  dst = wguT;  R = D_DIM; C = H_DIM; mul = 2; add = 0; bi = (size_t)e * R * C; bo = bi * 2; }
    else if (z < 32)  { int e = z - 16; src = wu;  dst = wguT;  R = D_DIM; C = H_DIM; mul = 2; add = 1; bi = (size_t)e * R * C; bo = bi * 2; }
    else if (z < 48)  { int e = z - 32; src = wd;  dst = wdT;   R = H_DIM; C = D_DIM; mul = 1; add = 0; bi = (size_t)e * R * C; bo = bi; }
    else if (z == 48) { src = swg; dst = swguT; R = D_DIM; C = H_DIM; mul = 2; add = 0; bi = 0; bo = 0; }
    else if (z == 49) { src = swu; dst = swguT; R = D_DIM; C = H_DIM; mul = 2; add = 1; bi = 0; bo = 0; }
    else              { src = swd; dst = swdT;  R = H_DIM; C = D_DIM; mul = 1; add = 0; bi = 0; bo = 0; }

    const int c0 = blockIdx.x * 32, r0 = blockIdx.y * 64;
    if (c0 >= C || r0 >= R) return;

    __shared__ float tile[32][65];
#pragma unroll
    for (int j = 0; j < 64; j += 8)
        tile[tx][ty + j] = src[bi + (size_t)(r0 + ty + j) * C + c0 + tx];
    __syncthreads();
#pragma unroll
    for (int jc = 0; jc < 4; jc++) {
        int c = ty + jc * 8;
        __half2 v = __floats2half2_rn(tile[c][2 * tx], tile[c][2 * tx + 1]);
        *(__half2*)(dst + bo + (size_t)((c0 + c) * mul + add) * R + r0 + 2 * tx) = v;
    }
}

// ---------------------------------------------------------------------------
// Gating (exact fp32). Also emits the fp16 copy of x (g_xt).
// ---------------------------------------------------------------------------
__global__ void gating_kernel(const float* __restrict__ x) {
    int n = blockIdx.x, t = threadIdx.x;
    int warp = t >> 5, lane = t & 31;
    __shared__ float sx[D_DIM];
    __shared__ float red[8];
    __shared__ float slog[E_NUM];
    const float* xr = x + (size_t)n * D_DIM;
    float ss = 0.f;
    for (int i = t; i < D_DIM; i += 256) { float v = xr[i]; sx[i] = v; ss += v * v; }
    for (int o = 16; o; o >>= 1) ss += __shfl_down_sync(0xFFFFFFFFu, ss, o);
    if (lane == 0) red[warp] = ss;
    __syncthreads();
    for (int i = t; i < D_DIM; i += 256) g_xt[(size_t)n * D_DIM + i] = __float2half_rn(sx[i]);
    for (int j = 0; j < 2; j++) {
        int e = warp * 2 + j;
        const float* g = g_gwn + e * D_DIM;
        float d = 0.f;
        for (int i = lane; i < D_DIM; i += 32) d += sx[i] * g[i];
        for (int o = 16; o; o >>= 1) d += __shfl_down_sync(0xFFFFFFFFu, d, o);
        if (lane == 0) slog[e] = d;
    }
    __syncthreads();
    if (t == 0) {
        float ssq = 0.f;
        for (int i = 0; i < 8; i++) ssq += red[i];
        float inv = 1.0f / fmaxf(sqrtf(ssq), 1e-12f);
        float sc[E_NUM];
        for (int e = 0; e < E_NUM; e++) sc[e] = slog[e] * inv;
        int sel[KSEL]; float sw[KSEL]; float wsum = 0.f;
        for (int k = 0; k < KSEL; k++) {
            int bi = 0; float bv = -1e30f;
            for (int e = 0; e < E_NUM; e++)
                if (sc[e] > bv) { bv = sc[e]; bi = e; }
            sel[k] = bi;
            float s = 1.0f / (1.0f + __expf(-bv));
            sw[k] = s; wsum += s; sc[bi] = -1e30f;
        }
        float invw = 1.0f / wsum;
        for (int k = 0; k < KSEL; k++) {
            g_idx[n * KSEL + k] = sel[k];
            g_w[n * KSEL + k]   = sw[k] * invw;
            atomicAdd(&g_cnt[sel[k]], 1);
        }
    }
}

// scatter with in-block prefix over g_cnt
__global__ void scatter_kernel() {
    __shared__ int soff[E_NUM];
    int t = threadIdx.x;
    if (t == 0) {
        int a = 0;
        for (int e = 0; e < E_NUM; e++) { soff[e] = a; a += g_cnt[e]; }
    }
    __syncthreads();
    int id = blockIdx.x * 256 + t;
    if (id < NK) {
        int e = g_idx[id];
        int p = soff[e] + atomicAdd(&g_pos[e], 1);
        g_tok[p] = id / KSEL;
        g_tw[p]  = g_w[id];
        g_pmap[id] = p;
    }
}

// ---------------------------------------------------------------------------
// fp16 mma.sync GEMM, merged routed+shared launch (z<16 routed, z==16 shared).
// Block 128x128, BK=64, warp grid 2x4, m16n8k16, 3-stage cp.async.
// NO min-blocks clause (smem already caps at 2 CTAs/SM; free the registers)
// + fragment ping-pong across ks steps (LDSM latency hidden under HMMA).
// ---------------------------------------------------------------------------
#define ROWB    144
#define TILE_HB (128 * ROWB)
#define NSTG    3
#define SMEM_BYTES (2 * NSTG * TILE_HB + 1024)

template <bool GU>
__global__ void __launch_bounds__(256)
mma_gemm(const __half* __restrict__ Art, const __half* __restrict__ Ash,
         const __half* __restrict__ Brt, const __half* __restrict__ Bsh,
         __half* __restrict__ outRt, void* __restrict__ outShv) {
    constexpr int KD = GU ? D_DIM : H_DIM;
    const int e = blockIdx.z;
    const bool gather = (e < E_NUM);
    const int cnt = gather ? g_cnt[e] : NTOK;
    const int m0  = blockIdx.x * 128;
    if (m0 >= cnt) return;
    int offr = 0;
    if (gather) {
        for (int q = 0; q < E_NUM; q++) offr += (q < e) ? g_cnt[q] : 0;
    }
    const int n0 = blockIdx.y * 128;

    const __half* A = gather ? Art : Ash;
    const __half* B = gather ? (Brt + (size_t)e * 1024 * KD) : Bsh;

    extern __shared__ char smc[];
    const uint32_t uA = smem_u32(smc);
    const uint32_t uB = uA + NSTG * TILE_HB;
    int*   rtok = (int*)(smc + 2 * NSTG * TILE_HB);
    float* twsh = (float*)(smc + 2 * NSTG * TILE_HB + 512);

    const int t = threadIdx.x;
    const int warp = t >> 5, lane = t & 31;
    const int wm = warp >> 2, wn = warp & 3;

    if (t < 128) {
        int gm = m0 + t;
        int cg = (gm < cnt) ? gm : 0;
        int src;
        if (GU) src = gather ? g_tok[offr + cg] : gm;
        else    src = gather ? (offr + gm) : gm;
        rtok[t] = src;
        twsh[t] = (GU && gather) ? g_tw[offr + cg] : 1.0f;
    }
    __syncthreads();

    const __half* aP[4];
    const __half* bP[4];
    uint32_t sOff[4];
#pragma unroll
    for (int j = 0; j < 4; j++) {
        int cidx = t + j * 256;
        int row = cidx >> 3, kc = cidx & 7;
        aP[j] = A + (size_t)rtok[row] * KD + kc * 8;
        bP[j] = B + (size_t)(n0 + row) * KD + kc * 8;
        sOff[j] = (uint32_t)(row * ROWB + kc * 16);
    }

    // per-warp ldsm base addresses (ks-invariant parts)
    const uint32_t aRow = wm * 64 + (lane & 7) + ((lane >> 3) & 1) * 8;
    const uint32_t aCol = (lane >> 4) * 16;
    const uint32_t bRow0 = wn * 32 + ((lane >> 4) & 1) * 8 + (lane & 7);
    const uint32_t bCol = ((lane >> 3) & 1) * 16;

#define LOADSTAGE(s, k0) do {                                       \
        _Pragma("unroll")                                           \
        for (int j = 0; j < 4; j++) {                               \
            cp16(uA + (s) * TILE_HB + sOff[j], aP[j] + (k0));       \
            cp16(uB + (s) * TILE_HB + sOff[j], bP[j] + (k0));       \
        }                                                           \
    } while (0)

    // fragment fetch for one ks step into buffer q
#define LOADFRAG(q, uAs, uBs, ks) do {                                          \
        _Pragma("unroll")                                                       \
        for (int mt = 0; mt < 4; mt++) {                                        \
            uint32_t ad = (uAs) + (aRow + mt * 16) * ROWB + (ks) * 32 + aCol;   \
            ldm4(afr[q][mt][0], afr[q][mt][1], afr[q][mt][2], afr[q][mt][3], ad); \
        }                                                                       \
        _Pragma("unroll")                                                       \
        for (int p = 0; p < 2; p++) {                                           \
            uint32_t ad = (uBs) + (bRow0 + p * 16) * ROWB + (ks) * 32 + bCol;   \
            ldm4(bfr[q][p][0], bfr[q][p][1], bfr[q][p][2], bfr[q][p][3], ad);   \
        }                                                                       \
    } while (0)

    float c[4][4][4] = {};
    uint32_t afr[2][4][4], bfr[2][2][4];

    const int NIT = KD / 64;
    LOADSTAGE(0, 0);  CP_COMMIT();
    LOADSTAGE(1, 64); CP_COMMIT();

    for (int i = 0; i < NIT; i++) {
        CP_WAIT1();
        __syncthreads();
        const int ld = i + 2;
        if (ld < NIT) LOADSTAGE(ld % NSTG, ld * 64);
        CP_COMMIT();

        const int s = i % NSTG;
        const uint32_t uAs = uA + s * TILE_HB;
        const uint32_t uBs = uB + s * TILE_HB;

        LOADFRAG(0, uAs, uBs, 0);
#pragma unroll
        for (int ks = 0; ks < 4; ks++) {
            const int cur = ks & 1;
            if (ks < 3) LOADFRAG(cur ^ 1, uAs, uBs, ks + 1);
#pragma unroll
            for (int mt = 0; mt < 4; mt++) {
#pragma unroll
                for (int nt = 0; nt < 4; nt++)
                    mma16(c[mt][nt], afr[cur][mt],
                          bfr[cur][nt >> 1][2 * (nt & 1)], bfr[cur][nt >> 1][2 * (nt & 1) + 1]);
            }
        }
    }
#undef LOADSTAGE
#undef LOADFRAG

#pragma unroll
    for (int mt = 0; mt < 4; mt++) {
        int r0 = wm * 64 + mt * 16 + (lane >> 2);
#pragma unroll
        for (int pass = 0; pass < 2; pass++) {
            int r = r0 + pass * 8;
            int gm = m0 + r;
            if (gm < cnt) {
                if (GU) {
                    float tw = twsh[r];
                    __half* orow = (gather ? outRt + (size_t)(offr + gm) * H_DIM
                                           : (__half*)outShv + (size_t)gm * H_DIM);
#pragma unroll
                    for (int nt = 0; nt < 4; nt++) {
                        float g = c[mt][nt][pass * 2];
                        float u = c[mt][nt][pass * 2 + 1];
                        int h = (n0 + wn * 32 + nt * 8) / 2 + (lane & 3);
                        orow[h] = __float2half_rn(tw * u * g / (1.0f + __expf(-g)));
                    }
                } else if (gather) {
                    __half* orow = outRt + (size_t)(offr + gm) * D_DIM;
#pragma unroll
                    for (int nt = 0; nt < 4; nt++) {
                        int n = n0 + wn * 32 + nt * 8 + 2 * (lane & 3);
                        *(__half2*)(orow + n) =
                            __floats2half2_rn(c[mt][nt][pass * 2], c[mt][nt][pass * 2 + 1]);
                    }
                } else {
                    float* orow = (float*)outShv + (size_t)gm * D_DIM;
#pragma unroll
                    for (int nt = 0; nt < 4; nt++) {
                        int n = n0 + wn * 32 + nt * 8 + 2 * (lane & 3);
                        *(float2*)(orow + n) =
                            make_float2(c[mt][nt][pass * 2], c[mt][nt][pass * 2 + 1]);
                    }
                }
            }
        }
    }
}

// ---------------------------------------------------------------------------
// combine: out[n] (shared result) += sum_k g_yh[pmap[n,k]]  (fp16 reads)
// ---------------------------------------------------------------------------
__global__ void combine_kernel(float* __restrict__ out) {
    const int n = blockIdx.x, t = threadIdx.x;
    __shared__ int pm[KSEL];
    if (t < KSEL) pm[t] = g_pmap[n * KSEL + t];
    __syncthreads();
    float4 acc = *(const float4*)(out + (size_t)n * D_DIM + t * 4);
#pragma unroll
    for (int k = 0; k < KSEL; k++) {
        const __half2* p = (const __half2*)(g_yh + (size_t)pm[k] * D_DIM + t * 4);
        float2 v0 = __half22float2(p[0]);
        float2 v1 = __half22float2(p[1]);
        acc.x += v0.x; acc.y += v0.y; acc.z += v1.x; acc.w += v1.y;
    }
    *(float4*)(out + (size_t)n * D_DIM + t * 4) = acc;
}

// ---------------------------------------------------------------------------
// Launch:  prep2(1) gating(2) scatter(3) GU(4) DN(5) combine(6)
// ---------------------------------------------------------------------------
extern "C" void kernel_launch(void* const* d_in, const int* in_sizes, int n_in,
                              void* d_out, int out_size) {
    (void)in_sizes; (void)n_in; (void)out_size;
    const float* x       = (const float*)d_in[0];
    const float* gate_w  = (const float*)d_in[1];
    const float* w_gate  = (const float*)d_in[2];
    const float* w_up    = (const float*)d_in[3];
    const float* w_down  = (const float*)d_in[4];
    const float* sw_gate = (const float*)d_in[5];
    const float* sw_up   = (const float*)d_in[6];
    const float* sw_down = (const float*)d_in[7];
    float* out = (float*)d_out;

    cudaFuncSetAttribute(mma_gemm<true>,  cudaFuncAttributeMaxDynamicSharedMemorySize, SMEM_BYTES);
    cudaFuncSetAttribute(mma_gemm<false>, cudaFuncAttributeMaxDynamicSharedMemorySize, SMEM_BYTES);

    __half* xt; __half* wguT; __half* wdT; __half* swguT; __half* swdT;
    __half* hbuf; __half* hsbuf; __half* ybuf;
    cudaGetSymbolAddress((void**)&xt,    g_xt);
    cudaGetSymbolAddress((void**)&wguT,  g_wguT);
    cudaGetSymbolAddress((void**)&wdT,   g_wdT);
    cudaGetSymbolAddress((void**)&swguT, g_swguT);
    cudaGetSymbolAddress((void**)&swdT,  g_swdT);
    cudaGetSymbolAddress((void**)&hbuf,  g_h);
    cudaGetSymbolAddress((void**)&hsbuf, g_hs);
    cudaGetSymbolAddress((void**)&ybuf,  g_yh);

    prep2_kernel<<<dim3(32, 16, 52), dim3(32, 8)>>>(
        gate_w, w_gate, w_up, w_down, sw_gate, sw_up, sw_down, wguT, wdT, swguT, swdT);
    gating_kernel<<<NTOK, 256>>>(x);
    scatter_kernel<<<(NK + 255) / 256, 256>>>();

    mma_gemm<true><<<dim3(32, 8, E_NUM + 1), 256, SMEM_BYTES>>>(
        xt, xt, wguT, swguT, hbuf, (void*)hsbuf);

    mma_gemm<false><<<dim3(32, 8, E_NUM + 1), 256, SMEM_BYTES>>>(
        hbuf, hsbuf, wdT, swdT, ybuf, (void*)out);

    combine_kernel<<<NTOK, 256>>>(out);
}